// round 6
// baseline (speedup 1.0000x reference)
#include <cuda_runtime.h>
#include <cuda_bf16.h>

// Problem constants
#define BSZ 2
#define SSZ 2048
#define ESZ 1024
#define HSZ 16
#define DSZ 64
#define TOKS (BSZ*SSZ)          // 4096
#define QKV_N (3*ESZ)           // 3072

// Scratch (no cudaMalloc allowed)
__device__ float g_qkv[(size_t)TOKS * QKV_N];   // 48 MB
__device__ float g_ctx[(size_t)TOKS * ESZ];     // 16 MB

// ---------------------------------------------------------------------------
// SGEMM: C[M,N] = A[M,K] @ B[K,N] + bias[N]   (all row-major, dims % tile == 0)
// 128x128 block tile, BK=16, 8x8 per-thread, 256 threads.
// ---------------------------------------------------------------------------
__global__ __launch_bounds__(256) void sgemm_bias(
    const float* __restrict__ A, const float* __restrict__ B,
    const float* __restrict__ bias, float* __restrict__ C,
    int M, int N, int K)
{
    const int BM = 128, BN = 128, BK = 16;
    __shared__ __align__(16) float As[BK][BM + 4];   // stored transposed: As[k][m]
    __shared__ __align__(16) float Bs[BK][BN];       // Bs[k][n]

    int tid = threadIdx.x;
    int tx = tid & 15;          // 0..15 -> 8 output cols each
    int ty = tid >> 4;          // 0..15 -> 8 output rows each
    int m0 = blockIdx.y * BM;
    int n0 = blockIdx.x * BN;

    int arow = tid >> 2;            // 0..63
    int acol = (tid & 3) << 2;      // 0,4,8,12
    int brow = tid >> 5;            // 0..7
    int bcol = (tid & 31) << 2;     // 0..124

    float acc[8][8];
    #pragma unroll
    for (int i = 0; i < 8; i++)
        #pragma unroll
        for (int j = 0; j < 8; j++) acc[i][j] = 0.f;

    for (int k0 = 0; k0 < K; k0 += BK) {
        #pragma unroll
        for (int p = 0; p < 2; p++) {
            int r = arow + p * 64;
            float4 a = *(const float4*)(A + (size_t)(m0 + r) * K + k0 + acol);
            As[acol + 0][r] = a.x;
            As[acol + 1][r] = a.y;
            As[acol + 2][r] = a.z;
            As[acol + 3][r] = a.w;
        }
        #pragma unroll
        for (int p = 0; p < 2; p++) {
            int r = brow + p * 8;
            *(float4*)(&Bs[r][bcol]) =
                *(const float4*)(B + (size_t)(k0 + r) * N + n0 + bcol);
        }
        __syncthreads();

        #pragma unroll
        for (int kk = 0; kk < BK; kk++) {
            float a[8], b[8];
            *(float4*)(a)     = *(const float4*)(&As[kk][ty * 8]);
            *(float4*)(a + 4) = *(const float4*)(&As[kk][ty * 8 + 4]);
            *(float4*)(b)     = *(const float4*)(&Bs[kk][tx * 8]);
            *(float4*)(b + 4) = *(const float4*)(&Bs[kk][tx * 8 + 4]);
            #pragma unroll
            for (int i = 0; i < 8; i++)
                #pragma unroll
                for (int j = 0; j < 8; j++)
                    acc[i][j] += a[i] * b[j];
        }
        __syncthreads();
    }

    float bv[8];
    *(float4*)(bv)     = *(const float4*)(bias + n0 + tx * 8);
    *(float4*)(bv + 4) = *(const float4*)(bias + n0 + tx * 8 + 4);
    #pragma unroll
    for (int i = 0; i < 8; i++) {
        float* cp = C + (size_t)(m0 + ty * 8 + i) * N + n0 + tx * 8;
        float4 o0 = make_float4(acc[i][0] + bv[0], acc[i][1] + bv[1],
                                acc[i][2] + bv[2], acc[i][3] + bv[3]);
        float4 o1 = make_float4(acc[i][4] + bv[4], acc[i][5] + bv[5],
                                acc[i][6] + bv[6], acc[i][7] + bv[7]);
        *(float4*)cp       = o0;
        *(float4*)(cp + 4) = o1;
    }
}

// ---------------------------------------------------------------------------
// Flash attention (causal, fp32). One CTA = 64 queries of one (b,h).
// Shared layouts: Qs[d][r] stride 68 (scaled by 1/sqrt(D) at load),
// Ks[d][c] stride 68 (reused as P[c][r] after scores), Vs[c][d] stride 64.
// Thread (ty,tx) of 16x16 owns score/output sub-tile rows ty*4..+3, cols tx*4..+3.
// ---------------------------------------------------------------------------
#define QK_STRIDE 68
#define SMEM_ATTN ((2 * 64 * QK_STRIDE + 64 * 64) * 4)   // 51200 bytes

__global__ __launch_bounds__(256) void flash_attn_kernel(
    const float* __restrict__ qkv, float* __restrict__ ctx)
{
    extern __shared__ __align__(16) float sm[];
    float* Qs = sm;                        // [64][68]
    float* Ks = sm + 64 * QK_STRIDE;       // [64][68], aliased as P[c][r]
    float* Vs = sm + 2 * 64 * QK_STRIDE;   // [64][64]

    int tid = threadIdx.x;
    int tx = tid & 15;
    int ty = tid >> 4;
    int qblk = blockIdx.x;         // 0..31
    int bh = blockIdx.y;           // 0..31
    int b = bh >> 4;
    int h = bh & 15;

    const size_t tokst = QKV_N;    // 3072 floats per token
    const float* qbase = qkv + (size_t)(b * SSZ) * tokst + h * DSZ;
    const float* kbase = qbase + ESZ;
    const float* vbase = qbase + 2 * ESZ;
    int qs = qblk * 64;

    // Load Q tile, transposed + pre-scaled
    {
        int col4 = tid & 15;       // d-group (4 floats)
        int row  = tid >> 4;       // 0..15
        const float sc = 0.125f;   // 1/sqrt(64)
        #pragma unroll
        for (int p = 0; p < 4; p++) {
            int r = row + p * 16;
            float4 q = *(const float4*)(qbase + (size_t)(qs + r) * tokst + col4 * 4);
            Qs[(col4 * 4 + 0) * QK_STRIDE + r] = q.x * sc;
            Qs[(col4 * 4 + 1) * QK_STRIDE + r] = q.y * sc;
            Qs[(col4 * 4 + 2) * QK_STRIDE + r] = q.z * sc;
            Qs[(col4 * 4 + 3) * QK_STRIDE + r] = q.w * sc;
        }
    }

    float acc[4][4];
    #pragma unroll
    for (int i = 0; i < 4; i++)
        #pragma unroll
        for (int j = 0; j < 4; j++) acc[i][j] = 0.f;
    float mrow[4] = {-1e30f, -1e30f, -1e30f, -1e30f};
    float lrow[4] = {0.f, 0.f, 0.f, 0.f};

    for (int kv = 0; kv <= qblk; kv++) {
        int ks = kv * 64;
        __syncthreads();   // protects P/V from previous iter (and Q on first)

        // Load K (transposed) and V (direct)
        {
            int col4 = tid & 15;
            int row  = tid >> 4;
            #pragma unroll
            for (int p = 0; p < 4; p++) {
                int c = row + p * 16;
                float4 k = *(const float4*)(kbase + (size_t)(ks + c) * tokst + col4 * 4);
                Ks[(col4 * 4 + 0) * QK_STRIDE + c] = k.x;
                Ks[(col4 * 4 + 1) * QK_STRIDE + c] = k.y;
                Ks[(col4 * 4 + 2) * QK_STRIDE + c] = k.z;
                Ks[(col4 * 4 + 3) * QK_STRIDE + c] = k.w;
                float4 v = *(const float4*)(vbase + (size_t)(ks + c) * tokst + col4 * 4);
                *(float4*)(&Vs[c * 64 + col4 * 4]) = v;
            }
        }
        __syncthreads();

        // S = Q @ K^T  (scaled already)
        float s[4][4];
        #pragma unroll
        for (int i = 0; i < 4; i++)
            #pragma unroll
            for (int j = 0; j < 4; j++) s[i][j] = 0.f;
        #pragma unroll 8
        for (int d = 0; d < 64; d++) {
            float4 qv = *(const float4*)(&Qs[d * QK_STRIDE + ty * 4]);
            float4 kw = *(const float4*)(&Ks[d * QK_STRIDE + tx * 4]);
            float qa[4] = {qv.x, qv.y, qv.z, qv.w};
            float kb[4] = {kw.x, kw.y, kw.z, kw.w};
            #pragma unroll
            for (int i = 0; i < 4; i++)
                #pragma unroll
                for (int j = 0; j < 4; j++)
                    s[i][j] += qa[i] * kb[j];
        }

        if (kv == qblk) {   // causal mask on diagonal block
            #pragma unroll
            for (int i = 0; i < 4; i++)
                #pragma unroll
                for (int j = 0; j < 4; j++)
                    if (tx * 4 + j > ty * 4 + i) s[i][j] = -1e30f;
        }

        // Online softmax (row reductions across tx via width-16 shuffles)
        float p[4][4];
        #pragma unroll
        for (int i = 0; i < 4; i++) {
            float mx = fmaxf(fmaxf(s[i][0], s[i][1]), fmaxf(s[i][2], s[i][3]));
            #pragma unroll
            for (int o = 8; o >= 1; o >>= 1)
                mx = fmaxf(mx, __shfl_xor_sync(0xffffffffu, mx, o, 16));
            float mnew = fmaxf(mrow[i], mx);
            float alpha = __expf(mrow[i] - mnew);
            float rs = 0.f;
            #pragma unroll
            for (int j = 0; j < 4; j++) {
                p[i][j] = __expf(s[i][j] - mnew);
                rs += p[i][j];
            }
            #pragma unroll
            for (int o = 8; o >= 1; o >>= 1)
                rs += __shfl_xor_sync(0xffffffffu, rs, o, 16);
            lrow[i] = lrow[i] * alpha + rs;
            mrow[i] = mnew;
            #pragma unroll
            for (int j = 0; j < 4; j++) acc[i][j] *= alpha;
        }

        __syncthreads();   // everyone done reading Ks
        // Write P into Ks buffer as P[c][r]
        #pragma unroll
        for (int j = 0; j < 4; j++)
            #pragma unroll
            for (int i = 0; i < 4; i++)
                Ks[(tx * 4 + j) * QK_STRIDE + ty * 4 + i] = p[i][j];
        __syncthreads();

        // O += P @ V
        #pragma unroll 8
        for (int c = 0; c < 64; c++) {
            float4 pv = *(const float4*)(&Ks[c * QK_STRIDE + ty * 4]);
            float4 vv = *(const float4*)(&Vs[c * 64 + tx * 4]);
            float pa[4] = {pv.x, pv.y, pv.z, pv.w};
            float vb[4] = {vv.x, vv.y, vv.z, vv.w};
            #pragma unroll
            for (int i = 0; i < 4; i++)
                #pragma unroll
                for (int j = 0; j < 4; j++)
                    acc[i][j] += pa[i] * vb[j];
        }
    }

    // Normalize and write ctx[b*S+s][h*D+d]
    #pragma unroll
    for (int i = 0; i < 4; i++) {
        float inv = 1.0f / lrow[i];
        float4 o = make_float4(acc[i][0] * inv, acc[i][1] * inv,
                               acc[i][2] * inv, acc[i][3] * inv);
        float* cp = ctx + (size_t)(b * SSZ + qs + ty * 4 + i) * ESZ + h * DSZ + tx * 4;
        *(float4*)cp = o;
    }
}

// ---------------------------------------------------------------------------
extern "C" void kernel_launch(void* const* d_in, const int* in_sizes, int n_in,
                              void* d_out, int out_size)
{
    const float* x      = (const float*)d_in[0];
    const float* W_attn = (const float*)d_in[1];
    const float* b_attn = (const float*)d_in[2];
    const float* W_proj = (const float*)d_in[3];
    const float* b_proj = (const float*)d_in[4];
    float* out = (float*)d_out;

    float *qkv, *ctx;
    cudaGetSymbolAddress((void**)&qkv, g_qkv);
    cudaGetSymbolAddress((void**)&ctx, g_ctx);

    // 1) QKV projection: (4096,1024) @ (1024,3072) + bias
    {
        dim3 grid(QKV_N / 128, TOKS / 128);
        sgemm_bias<<<grid, 256>>>(x, W_attn, b_attn, qkv, TOKS, QKV_N, ESZ);
    }

    // 2) Causal flash attention per (b,h)
    {
        cudaFuncSetAttribute(flash_attn_kernel,
                             cudaFuncAttributeMaxDynamicSharedMemorySize, SMEM_ATTN);
        dim3 grid(SSZ / 64, BSZ * HSZ);
        flash_attn_kernel<<<grid, 256, SMEM_ATTN>>>(qkv, ctx);
    }

    // 3) Output projection: (4096,1024) @ (1024,1024) + bias
    {
        dim3 grid(ESZ / 128, TOKS / 128);
        sgemm_bias<<<grid, 256>>>(ctx, W_proj, b_proj, out, TOKS, ESZ, ESZ);
    }
}

// round 12
// speedup vs baseline: 1.3255x; 1.3255x over previous
#include <cuda_runtime.h>
#include <cuda_bf16.h>
#include <cstdint>

// Problem constants
#define BSZ 2
#define SSZ 2048
#define ESZ 1024
#define HSZ 16
#define DSZ 64
#define TOKS (BSZ*SSZ)          // 4096
#define QKV_N (3*ESZ)           // 3072
#define KDIM 1024               // inner dim of both GEMMs

// ---------------------------------------------------------------------------
// Scratch (no cudaMalloc allowed)
// ---------------------------------------------------------------------------
__device__ float g_qkv[(size_t)TOKS * QKV_N];                  // 48 MB fp32
__device__ __nv_bfloat16 g_xa_hi[(size_t)TOKS * KDIM];
__device__ __nv_bfloat16 g_xa_lo[(size_t)TOKS * KDIM];
__device__ __nv_bfloat16 g_wat_hi[(size_t)QKV_N * KDIM];       // transposed [N][K]
__device__ __nv_bfloat16 g_wat_lo[(size_t)QKV_N * KDIM];
__device__ __nv_bfloat16 g_wpt_hi[(size_t)ESZ * KDIM];         // transposed [N][K]
__device__ __nv_bfloat16 g_wpt_lo[(size_t)ESZ * KDIM];
__device__ __nv_bfloat16 g_ctx_hi[(size_t)TOKS * ESZ];
__device__ __nv_bfloat16 g_ctx_lo[(size_t)TOKS * ESZ];

// ---------------------------------------------------------------------------
// PTX helpers (all plain-sm_80+ features: valid on compute_103 target)
// ---------------------------------------------------------------------------
__device__ __forceinline__ uint32_t smem_to_u32(const void* p) {
    uint32_t a;
    asm("{ .reg .u64 t; cvta.to.shared.u64 t, %1; cvt.u32.u64 %0, t; }" : "=r"(a) : "l"(p));
    return a;
}
__device__ __forceinline__ void ldmatrix_x4(uint32_t* r, uint32_t addr) {
    asm volatile("ldmatrix.sync.aligned.m8n8.x4.shared.b16 {%0,%1,%2,%3}, [%4];"
        : "=r"(r[0]), "=r"(r[1]), "=r"(r[2]), "=r"(r[3]) : "r"(addr));
}
__device__ __forceinline__ void mma_bf16(float* d, const uint32_t* a,
                                         uint32_t b0, uint32_t b1) {
    asm volatile("mma.sync.aligned.m16n8k16.row.col.f32.bf16.bf16.f32 "
        "{%0,%1,%2,%3}, {%4,%5,%6,%7}, {%8,%9}, {%0,%1,%2,%3};"
        : "+f"(d[0]), "+f"(d[1]), "+f"(d[2]), "+f"(d[3])
        : "r"(a[0]), "r"(a[1]), "r"(a[2]), "r"(a[3]), "r"(b0), "r"(b1));
}
__device__ __forceinline__ void cp_async16(uint32_t dst, const void* src) {
    asm volatile("cp.async.cg.shared.global [%0], [%1], 16;" :: "r"(dst), "l"(src));
}
#define CP_COMMIT()  asm volatile("cp.async.commit_group;" ::: "memory")
#define CP_WAIT_1()  asm volatile("cp.async.wait_group 1;" ::: "memory")
#define CP_WAIT_0()  asm volatile("cp.async.wait_group 0;" ::: "memory")

// ---------------------------------------------------------------------------
// fp32 -> (hi, lo) bf16 split, elementwise (for activations)
// ---------------------------------------------------------------------------
__global__ __launch_bounds__(256) void split_f32(
    const float4* __restrict__ in, __nv_bfloat16* __restrict__ hi,
    __nv_bfloat16* __restrict__ lo)
{
    int i = blockIdx.x * 256 + threadIdx.x;
    float4 v = in[i];
    float a[4] = {v.x, v.y, v.z, v.w};
    int o = i * 4;
    #pragma unroll
    for (int j = 0; j < 4; j += 2) {
        __nv_bfloat16 h0 = __float2bfloat16(a[j]);
        __nv_bfloat16 h1 = __float2bfloat16(a[j + 1]);
        __nv_bfloat162 hp; hp.x = h0; hp.y = h1;
        *(__nv_bfloat162*)(hi + o + j) = hp;
        __nv_bfloat162 lp;
        lp.x = __float2bfloat16(a[j] - __bfloat162float(h0));
        lp.y = __float2bfloat16(a[j + 1] - __bfloat162float(h1));
        *(__nv_bfloat162*)(lo + o + j) = lp;
    }
}

// ---------------------------------------------------------------------------
// fp32 W[K][N] -> transposed (hi, lo) bf16 [N][K]
// ---------------------------------------------------------------------------
__global__ __launch_bounds__(256) void split_transpose(
    const float* __restrict__ W, __nv_bfloat16* __restrict__ Th,
    __nv_bfloat16* __restrict__ Tl, int Ncols)
{
    __shared__ float t[32][33];
    int n0 = blockIdx.x * 32, k0 = blockIdx.y * 32;
    int tx = threadIdx.x, ty = threadIdx.y;      // 32 x 8
    #pragma unroll
    for (int p = 0; p < 4; p++)
        t[ty + p * 8][tx] = W[(size_t)(k0 + ty + p * 8) * Ncols + n0 + tx];
    __syncthreads();
    #pragma unroll
    for (int p = 0; p < 4; p++) {
        float v = t[tx][ty + p * 8];
        __nv_bfloat16 h = __float2bfloat16(v);
        size_t o = (size_t)(n0 + ty + p * 8) * KDIM + k0 + tx;
        Th[o] = h;
        Tl[o] = __float2bfloat16(v - __bfloat162float(h));
    }
}

// ---------------------------------------------------------------------------
// mma.sync bf16-split GEMM: C[M,N] = Ah@Bh^T + Ah@Bl^T + Al@Bh^T + bias
// A*: [M][1024] bf16 row-major.  B*: [N][1024] bf16 (logical W transposed).
// CTA 128x128, BK=32, 8 warps (4m x 2n), warp tile 32x64.
// Smem row stride 40 bf16 (80B): 16B-aligned + conflict-free ldmatrix.
// 2-stage cp.async pipeline.
// ---------------------------------------------------------------------------
#define TILE_B 10240                 // 128 rows * 80 B
#define STAGE_B (4 * TILE_B)         // Ah, Al, Bh, Bl
#define GEMM_SMEM (2 * STAGE_B)      // 81920 B

__global__ __launch_bounds__(256, 1) void gemm_mma_split(
    const __nv_bfloat16* __restrict__ Ah, const __nv_bfloat16* __restrict__ Al,
    const __nv_bfloat16* __restrict__ Bh, const __nv_bfloat16* __restrict__ Bl,
    const float* __restrict__ bias, float* __restrict__ C, int N)
{
    extern __shared__ char sm[];
    uint32_t smb = smem_to_u32(sm);
    int tid = threadIdx.x, wid = tid >> 5, lane = tid & 31;
    int wm = wid & 3, wn = wid >> 2;           // warp coords: 4 x 2
    int m0 = blockIdx.y * 128, n0 = blockIdx.x * 128;

    const __nv_bfloat16* gsrc[4] = {
        Ah + (size_t)m0 * KDIM, Al + (size_t)m0 * KDIM,
        Bh + (size_t)n0 * KDIM, Bl + (size_t)n0 * KDIM };

    // ldmatrix lane addressing: row = lane%16, k-half = lane/16
    int lrow = lane & 15, khalf = lane >> 4;

    float acc[2][8][4];
    #pragma unroll
    for (int mt = 0; mt < 2; mt++)
        #pragma unroll
        for (int nt = 0; nt < 8; nt++)
            #pragma unroll
            for (int c = 0; c < 4; c++) acc[mt][nt][c] = 0.f;

    // issue loads for one chunk into stage s
    auto load_chunk = [&](int k0c, int s) {
        uint32_t stb = smb + s * STAGE_B;
        #pragma unroll
        for (int tile = 0; tile < 4; tile++) {
            const __nv_bfloat16* gb = gsrc[tile];
            #pragma unroll
            for (int p = 0; p < 2; p++) {
                int op = p * 256 + tid;
                int row = op >> 2, kg = op & 3;         // kg: 16B group (8 bf16)
                cp_async16(stb + tile * TILE_B + row * 80 + kg * 16,
                           gb + (size_t)row * KDIM + k0c + kg * 8);
            }
        }
        CP_COMMIT();
    };

    load_chunk(0, 0);

    const int NCHUNK = KDIM / 32;   // 32
    for (int ch = 0; ch < NCHUNK; ch++) {
        int s = ch & 1;
        if (ch + 1 < NCHUNK) {
            load_chunk((ch + 1) * 32, s ^ 1);
            CP_WAIT_1();
        } else {
            CP_WAIT_0();
        }
        __syncthreads();

        uint32_t stb = smb + s * STAGE_B;
        uint32_t sAh = stb;
        uint32_t sAl = stb + TILE_B;
        uint32_t sBh = stb + 2 * TILE_B;
        uint32_t sBl = stb + 3 * TILE_B;

        #pragma unroll
        for (int ks = 0; ks < 2; ks++) {
            int koff = ks * 32 + khalf * 16;   // bytes within row

            uint32_t ah[2][4], al[2][4];
            #pragma unroll
            for (int mt = 0; mt < 2; mt++) {
                uint32_t ro = (wm * 32 + mt * 16 + lrow) * 80 + koff;
                ldmatrix_x4(ah[mt], sAh + ro);
                ldmatrix_x4(al[mt], sAl + ro);
            }
            uint32_t bh[4][4], bl[4][4];
            #pragma unroll
            for (int g = 0; g < 4; g++) {
                uint32_t ro = (wn * 64 + g * 16 + lrow) * 80 + koff;
                ldmatrix_x4(bh[g], sBh + ro);
                ldmatrix_x4(bl[g], sBl + ro);
            }

            #pragma unroll
            for (int mt = 0; mt < 2; mt++)
                #pragma unroll
                for (int nt = 0; nt < 8; nt++) {
                    int g = nt >> 1, o = nt & 1;
                    mma_bf16(acc[mt][nt], ah[mt], bh[g][o], bh[g][2 + o]);   // hi*hi
                    mma_bf16(acc[mt][nt], ah[mt], bl[g][o], bl[g][2 + o]);   // hi*lo
                    mma_bf16(acc[mt][nt], al[mt], bh[g][o], bh[g][2 + o]);   // lo*hi
                }
        }
        __syncthreads();
    }

    // Epilogue: acc layout — thread holds (row t/4 [+8], col (t%4)*2 [+1])
    int tq = lane >> 2, tr = lane & 3;
    #pragma unroll
    for (int mt = 0; mt < 2; mt++) {
        int rbase = m0 + wm * 32 + mt * 16 + tq;
        #pragma unroll
        for (int nt = 0; nt < 8; nt++) {
            int col = n0 + wn * 64 + nt * 8 + tr * 2;
            float2 bv = *(const float2*)(bias + col);
            float2 o0 = make_float2(acc[mt][nt][0] + bv.x, acc[mt][nt][1] + bv.y);
            float2 o1 = make_float2(acc[mt][nt][2] + bv.x, acc[mt][nt][3] + bv.y);
            *(float2*)(C + (size_t)rbase * N + col)       = o0;
            *(float2*)(C + (size_t)(rbase + 8) * N + col) = o1;
        }
    }
}

// ---------------------------------------------------------------------------
// Flash attention (causal, fp32). Writes ctx as (hi, lo) bf16 split.
// ---------------------------------------------------------------------------
#define QK_STRIDE 68
#define SMEM_ATTN ((2 * 64 * QK_STRIDE + 64 * 64) * 4)   // 51200 bytes

__global__ __launch_bounds__(256) void flash_attn_kernel(
    const float* __restrict__ qkv,
    __nv_bfloat16* __restrict__ ctx_hi, __nv_bfloat16* __restrict__ ctx_lo)
{
    extern __shared__ __align__(16) float smf[];
    float* Qs = smf;
    float* Ks = smf + 64 * QK_STRIDE;
    float* Vs = smf + 2 * 64 * QK_STRIDE;

    int tid = threadIdx.x;
    int tx = tid & 15;
    int ty = tid >> 4;
    int qblk = blockIdx.x;
    int bh = blockIdx.y;
    int b = bh >> 4;
    int h = bh & 15;

    const size_t tokst = QKV_N;
    const float* qbase = qkv + (size_t)(b * SSZ) * tokst + h * DSZ;
    const float* kbase = qbase + ESZ;
    const float* vbase = qbase + 2 * ESZ;
    int qs = qblk * 64;

    {
        int col4 = tid & 15;
        int row  = tid >> 4;
        const float sc = 0.125f;
        #pragma unroll
        for (int p = 0; p < 4; p++) {
            int r = row + p * 16;
            float4 q = *(const float4*)(qbase + (size_t)(qs + r) * tokst + col4 * 4);
            Qs[(col4 * 4 + 0) * QK_STRIDE + r] = q.x * sc;
            Qs[(col4 * 4 + 1) * QK_STRIDE + r] = q.y * sc;
            Qs[(col4 * 4 + 2) * QK_STRIDE + r] = q.z * sc;
            Qs[(col4 * 4 + 3) * QK_STRIDE + r] = q.w * sc;
        }
    }

    float acc[4][4];
    #pragma unroll
    for (int i = 0; i < 4; i++)
        #pragma unroll
        for (int j = 0; j < 4; j++) acc[i][j] = 0.f;
    float mrow[4] = {-1e30f, -1e30f, -1e30f, -1e30f};
    float lrow[4] = {0.f, 0.f, 0.f, 0.f};

    for (int kv = 0; kv <= qblk; kv++) {
        int ks = kv * 64;
        __syncthreads();

        {
            int col4 = tid & 15;
            int row  = tid >> 4;
            #pragma unroll
            for (int p = 0; p < 4; p++) {
                int c = row + p * 16;
                float4 k = *(const float4*)(kbase + (size_t)(ks + c) * tokst + col4 * 4);
                Ks[(col4 * 4 + 0) * QK_STRIDE + c] = k.x;
                Ks[(col4 * 4 + 1) * QK_STRIDE + c] = k.y;
                Ks[(col4 * 4 + 2) * QK_STRIDE + c] = k.z;
                Ks[(col4 * 4 + 3) * QK_STRIDE + c] = k.w;
                float4 v = *(const float4*)(vbase + (size_t)(ks + c) * tokst + col4 * 4);
                *(float4*)(&Vs[c * 64 + col4 * 4]) = v;
            }
        }
        __syncthreads();

        float s[4][4];
        #pragma unroll
        for (int i = 0; i < 4; i++)
            #pragma unroll
            for (int j = 0; j < 4; j++) s[i][j] = 0.f;
        #pragma unroll 8
        for (int d = 0; d < 64; d++) {
            float4 qv = *(const float4*)(&Qs[d * QK_STRIDE + ty * 4]);
            float4 kw = *(const float4*)(&Ks[d * QK_STRIDE + tx * 4]);
            float qa[4] = {qv.x, qv.y, qv.z, qv.w};
            float kb[4] = {kw.x, kw.y, kw.z, kw.w};
            #pragma unroll
            for (int i = 0; i < 4; i++)
                #pragma unroll
                for (int j = 0; j < 4; j++)
                    s[i][j] += qa[i] * kb[j];
        }

        if (kv == qblk) {
            #pragma unroll
            for (int i = 0; i < 4; i++)
                #pragma unroll
                for (int j = 0; j < 4; j++)
                    if (tx * 4 + j > ty * 4 + i) s[i][j] = -1e30f;
        }

        float p[4][4];
        #pragma unroll
        for (int i = 0; i < 4; i++) {
            float mx = fmaxf(fmaxf(s[i][0], s[i][1]), fmaxf(s[i][2], s[i][3]));
            #pragma unroll
            for (int o = 8; o >= 1; o >>= 1)
                mx = fmaxf(mx, __shfl_xor_sync(0xffffffffu, mx, o, 16));
            float mnew = fmaxf(mrow[i], mx);
            float alpha = __expf(mrow[i] - mnew);
            float rs = 0.f;
            #pragma unroll
            for (int j = 0; j < 4; j++) {
                p[i][j] = __expf(s[i][j] - mnew);
                rs += p[i][j];
            }
            #pragma unroll
            for (int o = 8; o >= 1; o >>= 1)
                rs += __shfl_xor_sync(0xffffffffu, rs, o, 16);
            lrow[i] = lrow[i] * alpha + rs;
            mrow[i] = mnew;
            #pragma unroll
            for (int j = 0; j < 4; j++) acc[i][j] *= alpha;
        }

        __syncthreads();
        #pragma unroll
        for (int j = 0; j < 4; j++)
            #pragma unroll
            for (int i = 0; i < 4; i++)
                Ks[(tx * 4 + j) * QK_STRIDE + ty * 4 + i] = p[i][j];
        __syncthreads();

        #pragma unroll 8
        for (int c = 0; c < 64; c++) {
            float4 pv = *(const float4*)(&Ks[c * QK_STRIDE + ty * 4]);
            float4 vv = *(const float4*)(&Vs[c * 64 + tx * 4]);
            float pa[4] = {pv.x, pv.y, pv.z, pv.w};
            float vb[4] = {vv.x, vv.y, vv.z, vv.w};
            #pragma unroll
            for (int i = 0; i < 4; i++)
                #pragma unroll
                for (int j = 0; j < 4; j++)
                    acc[i][j] += pa[i] * vb[j];
        }
    }

    #pragma unroll
    for (int i = 0; i < 4; i++) {
        float inv = 1.0f / lrow[i];
        float v[4] = {acc[i][0] * inv, acc[i][1] * inv, acc[i][2] * inv, acc[i][3] * inv};
        size_t off = (size_t)(b * SSZ + qs + ty * 4 + i) * ESZ + h * DSZ + tx * 4;
        #pragma unroll
        for (int j = 0; j < 4; j += 2) {
            __nv_bfloat16 h0 = __float2bfloat16(v[j]);
            __nv_bfloat16 h1 = __float2bfloat16(v[j + 1]);
            __nv_bfloat162 hp; hp.x = h0; hp.y = h1;
            *(__nv_bfloat162*)(ctx_hi + off + j) = hp;
            __nv_bfloat162 lp;
            lp.x = __float2bfloat16(v[j] - __bfloat162float(h0));
            lp.y = __float2bfloat16(v[j + 1] - __bfloat162float(h1));
            *(__nv_bfloat162*)(ctx_lo + off + j) = lp;
        }
    }
}

// ---------------------------------------------------------------------------
extern "C" void kernel_launch(void* const* d_in, const int* in_sizes, int n_in,
                              void* d_out, int out_size)
{
    const float* x      = (const float*)d_in[0];
    const float* W_attn = (const float*)d_in[1];
    const float* b_attn = (const float*)d_in[2];
    const float* W_proj = (const float*)d_in[3];
    const float* b_proj = (const float*)d_in[4];
    float* out = (float*)d_out;

    float* qkv;
    __nv_bfloat16 *xa_hi, *xa_lo, *wat_hi, *wat_lo, *wpt_hi, *wpt_lo, *ctx_hi, *ctx_lo;
    cudaGetSymbolAddress((void**)&qkv, g_qkv);
    cudaGetSymbolAddress((void**)&xa_hi, g_xa_hi);
    cudaGetSymbolAddress((void**)&xa_lo, g_xa_lo);
    cudaGetSymbolAddress((void**)&wat_hi, g_wat_hi);
    cudaGetSymbolAddress((void**)&wat_lo, g_wat_lo);
    cudaGetSymbolAddress((void**)&wpt_hi, g_wpt_hi);
    cudaGetSymbolAddress((void**)&wpt_lo, g_wpt_lo);
    cudaGetSymbolAddress((void**)&ctx_hi, g_ctx_hi);
    cudaGetSymbolAddress((void**)&ctx_lo, g_ctx_lo);

    cudaFuncSetAttribute(gemm_mma_split,
                         cudaFuncAttributeMaxDynamicSharedMemorySize, GEMM_SMEM);
    cudaFuncSetAttribute(flash_attn_kernel,
                         cudaFuncAttributeMaxDynamicSharedMemorySize, SMEM_ATTN);

    // 0) fp32 -> bf16 hi/lo splits (x elementwise, W transposed to [N][K])
    split_f32<<<(TOKS * KDIM) / (256 * 4), 256>>>((const float4*)x, xa_hi, xa_lo);
    split_transpose<<<dim3(QKV_N / 32, KDIM / 32), dim3(32, 8)>>>(W_attn, wat_hi, wat_lo, QKV_N);
    split_transpose<<<dim3(ESZ / 32, KDIM / 32), dim3(32, 8)>>>(W_proj, wpt_hi, wpt_lo, ESZ);

    // 1) QKV projection on tensor cores (mma.sync bf16 split)
    gemm_mma_split<<<dim3(QKV_N / 128, TOKS / 128), 256, GEMM_SMEM>>>(
        xa_hi, xa_lo, wat_hi, wat_lo, b_attn, qkv, QKV_N);

    // 2) Causal flash attention per (b,h); writes ctx hi/lo bf16
    flash_attn_kernel<<<dim3(SSZ / 64, BSZ * HSZ), 256, SMEM_ATTN>>>(qkv, ctx_hi, ctx_lo);

    // 3) Output projection on tensor cores
    gemm_mma_split<<<dim3(ESZ / 128, TOKS / 128), 256, GEMM_SMEM>>>(
        ctx_hi, ctx_lo, wpt_hi, wpt_lo, b_proj, out, ESZ);
}

// round 14
// speedup vs baseline: 2.4512x; 1.8492x over previous
#include <cuda_runtime.h>
#include <cuda_bf16.h>
#include <cstdint>

// Problem constants
#define BSZ 2
#define SSZ 2048
#define ESZ 1024
#define HSZ 16
#define DSZ 64
#define TOKS (BSZ*SSZ)          // 4096
#define QKV_N (3*ESZ)           // 3072
#define KDIM 1024               // inner dim of both GEMMs

// ---------------------------------------------------------------------------
// Scratch (no cudaMalloc allowed)
// ---------------------------------------------------------------------------
__device__ __nv_bfloat16 g_qkv_hi[(size_t)TOKS * QKV_N];       // 24 MB
__device__ __nv_bfloat16 g_qkv_lo[(size_t)TOKS * QKV_N];       // 24 MB
__device__ __nv_bfloat16 g_xa_hi[(size_t)TOKS * KDIM];
__device__ __nv_bfloat16 g_xa_lo[(size_t)TOKS * KDIM];
__device__ __nv_bfloat16 g_wat_hi[(size_t)QKV_N * KDIM];       // transposed [N][K]
__device__ __nv_bfloat16 g_wat_lo[(size_t)QKV_N * KDIM];
__device__ __nv_bfloat16 g_wpt_hi[(size_t)ESZ * KDIM];         // transposed [N][K]
__device__ __nv_bfloat16 g_wpt_lo[(size_t)ESZ * KDIM];
__device__ __nv_bfloat16 g_ctx_hi[(size_t)TOKS * ESZ];
__device__ __nv_bfloat16 g_ctx_lo[(size_t)TOKS * ESZ];

// ---------------------------------------------------------------------------
// PTX helpers (all plain-sm_80+ features: valid on compute_103 target)
// ---------------------------------------------------------------------------
__device__ __forceinline__ uint32_t smem_to_u32(const void* p) {
    uint32_t a;
    asm("{ .reg .u64 t; cvta.to.shared.u64 t, %1; cvt.u32.u64 %0, t; }" : "=r"(a) : "l"(p));
    return a;
}
__device__ __forceinline__ void ldmatrix_x4(uint32_t* r, uint32_t addr) {
    asm volatile("ldmatrix.sync.aligned.m8n8.x4.shared.b16 {%0,%1,%2,%3}, [%4];"
        : "=r"(r[0]), "=r"(r[1]), "=r"(r[2]), "=r"(r[3]) : "r"(addr));
}
__device__ __forceinline__ void ldmatrix_x4_trans(uint32_t* r, uint32_t addr) {
    asm volatile("ldmatrix.sync.aligned.m8n8.x4.trans.shared.b16 {%0,%1,%2,%3}, [%4];"
        : "=r"(r[0]), "=r"(r[1]), "=r"(r[2]), "=r"(r[3]) : "r"(addr));
}
__device__ __forceinline__ void mma_bf16(float* d, const uint32_t* a,
                                         uint32_t b0, uint32_t b1) {
    asm volatile("mma.sync.aligned.m16n8k16.row.col.f32.bf16.bf16.f32 "
        "{%0,%1,%2,%3}, {%4,%5,%6,%7}, {%8,%9}, {%0,%1,%2,%3};"
        : "+f"(d[0]), "+f"(d[1]), "+f"(d[2]), "+f"(d[3])
        : "r"(a[0]), "r"(a[1]), "r"(a[2]), "r"(a[3]), "r"(b0), "r"(b1));
}
__device__ __forceinline__ void cp_async16(uint32_t dst, const void* src) {
    asm volatile("cp.async.cg.shared.global [%0], [%1], 16;" :: "r"(dst), "l"(src));
}
#define CP_COMMIT()  asm volatile("cp.async.commit_group;" ::: "memory")
#define CP_WAIT_1()  asm volatile("cp.async.wait_group 1;" ::: "memory")
#define CP_WAIT_0()  asm volatile("cp.async.wait_group 0;" ::: "memory")

// fp32 pair -> packed bf16x2 hi and lo
__device__ __forceinline__ void split2(float a, float b, uint32_t& hi, uint32_t& lo) {
    __nv_bfloat162 h = __floats2bfloat162_rn(a, b);
    __nv_bfloat162 l = __floats2bfloat162_rn(a - __bfloat162float(h.x),
                                             b - __bfloat162float(h.y));
    hi = *(uint32_t*)&h;
    lo = *(uint32_t*)&l;
}

// ---------------------------------------------------------------------------
// fp32 -> (hi, lo) bf16 split, elementwise (for activations)
// ---------------------------------------------------------------------------
__global__ __launch_bounds__(256) void split_f32(
    const float4* __restrict__ in, __nv_bfloat16* __restrict__ hi,
    __nv_bfloat16* __restrict__ lo)
{
    int i = blockIdx.x * 256 + threadIdx.x;
    float4 v = in[i];
    int o = i * 4;
    uint32_t h0, l0, h1, l1;
    split2(v.x, v.y, h0, l0);
    split2(v.z, v.w, h1, l1);
    *(uint32_t*)(hi + o)     = h0;
    *(uint32_t*)(hi + o + 2) = h1;
    *(uint32_t*)(lo + o)     = l0;
    *(uint32_t*)(lo + o + 2) = l1;
}

// ---------------------------------------------------------------------------
// fp32 W[K][N] -> transposed (hi, lo) bf16 [N][K]
// ---------------------------------------------------------------------------
__global__ __launch_bounds__(256) void split_transpose(
    const float* __restrict__ W, __nv_bfloat16* __restrict__ Th,
    __nv_bfloat16* __restrict__ Tl, int Ncols)
{
    __shared__ float t[32][33];
    int n0 = blockIdx.x * 32, k0 = blockIdx.y * 32;
    int tx = threadIdx.x, ty = threadIdx.y;      // 32 x 8
    #pragma unroll
    for (int p = 0; p < 4; p++)
        t[ty + p * 8][tx] = W[(size_t)(k0 + ty + p * 8) * Ncols + n0 + tx];
    __syncthreads();
    #pragma unroll
    for (int p = 0; p < 4; p++) {
        float v = t[tx][ty + p * 8];
        __nv_bfloat16 h = __float2bfloat16(v);
        size_t o = (size_t)(n0 + ty + p * 8) * KDIM + k0 + tx;
        Th[o] = h;
        Tl[o] = __float2bfloat16(v - __bfloat162float(h));
    }
}

// ---------------------------------------------------------------------------
// mma.sync bf16-split GEMM: C = Ah@Bh^T + Ah@Bl^T + Al@Bh^T + bias
// Output: fp32 C (if Chi==nullptr) else bf16 hi/lo split (Chi/Clo).
// CTA 128x128, BK=32, 8 warps (4m x 2n), warp tile 32x64. 2-stage cp.async.
// ---------------------------------------------------------------------------
#define TILE_B 10240                 // 128 rows * 80 B
#define STAGE_B (4 * TILE_B)         // Ah, Al, Bh, Bl
#define GEMM_SMEM (2 * STAGE_B)      // 81920 B

__global__ __launch_bounds__(256, 1) void gemm_mma_split(
    const __nv_bfloat16* __restrict__ Ah, const __nv_bfloat16* __restrict__ Al,
    const __nv_bfloat16* __restrict__ Bh, const __nv_bfloat16* __restrict__ Bl,
    const float* __restrict__ bias, float* __restrict__ C,
    __nv_bfloat16* __restrict__ Chi, __nv_bfloat16* __restrict__ Clo, int N)
{
    extern __shared__ char sm[];
    uint32_t smb = smem_to_u32(sm);
    int tid = threadIdx.x, wid = tid >> 5, lane = tid & 31;
    int wm = wid & 3, wn = wid >> 2;           // warp coords: 4 x 2
    int m0 = blockIdx.y * 128, n0 = blockIdx.x * 128;

    const __nv_bfloat16* gsrc[4] = {
        Ah + (size_t)m0 * KDIM, Al + (size_t)m0 * KDIM,
        Bh + (size_t)n0 * KDIM, Bl + (size_t)n0 * KDIM };

    int lrow = lane & 15, khalf = lane >> 4;

    float acc[2][8][4];
    #pragma unroll
    for (int mt = 0; mt < 2; mt++)
        #pragma unroll
        for (int nt = 0; nt < 8; nt++)
            #pragma unroll
            for (int c = 0; c < 4; c++) acc[mt][nt][c] = 0.f;

    auto load_chunk = [&](int k0c, int s) {
        uint32_t stb = smb + s * STAGE_B;
        #pragma unroll
        for (int tile = 0; tile < 4; tile++) {
            const __nv_bfloat16* gb = gsrc[tile];
            #pragma unroll
            for (int p = 0; p < 2; p++) {
                int op = p * 256 + tid;
                int row = op >> 2, kg = op & 3;
                cp_async16(stb + tile * TILE_B + row * 80 + kg * 16,
                           gb + (size_t)row * KDIM + k0c + kg * 8);
            }
        }
        CP_COMMIT();
    };

    load_chunk(0, 0);

    const int NCHUNK = KDIM / 32;   // 32
    for (int ch = 0; ch < NCHUNK; ch++) {
        int s = ch & 1;
        if (ch + 1 < NCHUNK) {
            load_chunk((ch + 1) * 32, s ^ 1);
            CP_WAIT_1();
        } else {
            CP_WAIT_0();
        }
        __syncthreads();

        uint32_t stb = smb + s * STAGE_B;
        uint32_t sAh = stb;
        uint32_t sAl = stb + TILE_B;
        uint32_t sBh = stb + 2 * TILE_B;
        uint32_t sBl = stb + 3 * TILE_B;

        #pragma unroll
        for (int ks = 0; ks < 2; ks++) {
            int koff = ks * 32 + khalf * 16;

            uint32_t ah[2][4], al[2][4];
            #pragma unroll
            for (int mt = 0; mt < 2; mt++) {
                uint32_t ro = (wm * 32 + mt * 16 + lrow) * 80 + koff;
                ldmatrix_x4(ah[mt], sAh + ro);
                ldmatrix_x4(al[mt], sAl + ro);
            }
            uint32_t bh[4][4], bl[4][4];
            #pragma unroll
            for (int g = 0; g < 4; g++) {
                uint32_t ro = (wn * 64 + g * 16 + lrow) * 80 + koff;
                ldmatrix_x4(bh[g], sBh + ro);
                ldmatrix_x4(bl[g], sBl + ro);
            }

            #pragma unroll
            for (int mt = 0; mt < 2; mt++)
                #pragma unroll
                for (int nt = 0; nt < 8; nt++) {
                    int g = nt >> 1, o = nt & 1;
                    mma_bf16(acc[mt][nt], ah[mt], bh[g][o], bh[g][2 + o]);   // hi*hi
                    mma_bf16(acc[mt][nt], ah[mt], bl[g][o], bl[g][2 + o]);   // hi*lo
                    mma_bf16(acc[mt][nt], al[mt], bh[g][o], bh[g][2 + o]);   // lo*hi
                }
        }
        __syncthreads();
    }

    // Epilogue
    int tq = lane >> 2, tr = lane & 3;
    #pragma unroll
    for (int mt = 0; mt < 2; mt++) {
        int rbase = m0 + wm * 32 + mt * 16 + tq;
        #pragma unroll
        for (int nt = 0; nt < 8; nt++) {
            int col = n0 + wn * 64 + nt * 8 + tr * 2;
            float2 bv = *(const float2*)(bias + col);
            float v0 = acc[mt][nt][0] + bv.x, v1 = acc[mt][nt][1] + bv.y;
            float v2 = acc[mt][nt][2] + bv.x, v3 = acc[mt][nt][3] + bv.y;
            if (Chi) {
                uint32_t h0, l0, h1, l1;
                split2(v0, v1, h0, l0);
                split2(v2, v3, h1, l1);
                size_t o0 = (size_t)rbase * N + col;
                size_t o1 = (size_t)(rbase + 8) * N + col;
                *(uint32_t*)(Chi + o0) = h0;  *(uint32_t*)(Clo + o0) = l0;
                *(uint32_t*)(Chi + o1) = h1;  *(uint32_t*)(Clo + o1) = l1;
            } else {
                *(float2*)(C + (size_t)rbase * N + col)       = make_float2(v0, v1);
                *(float2*)(C + (size_t)(rbase + 8) * N + col) = make_float2(v2, v3);
            }
        }
    }
}

// ---------------------------------------------------------------------------
// Tensor-core flash attention (causal). CTA = 128 q rows x one (b,h).
// 8 warps x 16 rows. Bc=64. All GEMMs via mma.sync with 2-term bf16 split.
// Smem rows stride 144 B (72 bf16) -> conflict-free ldmatrix.
// ---------------------------------------------------------------------------
#define SROWB 144
#define AQ_H 0
#define AQ_L 18432
#define ASTG0 36864                     // 2 stages of 36864 after Q
#define ASTG_SZ 36864
#define AKH 0
#define AKL 9216
#define AVH 18432
#define AVL 27648
#define SMEM_FA (ASTG0 + 2 * ASTG_SZ)   // 110592 B

__global__ __launch_bounds__(256, 1) void flash_mma_kernel(
    const __nv_bfloat16* __restrict__ qkv_hi,
    const __nv_bfloat16* __restrict__ qkv_lo,
    __nv_bfloat16* __restrict__ ctx_hi,
    __nv_bfloat16* __restrict__ ctx_lo)
{
    extern __shared__ char sm[];
    uint32_t smb = smem_to_u32(sm);
    int tid = threadIdx.x, wid = tid >> 5, lane = tid & 31;
    int bh = blockIdx.x;
    int b = bh >> 4, h = bh & 15;
    int qblk = (gridDim.y - 1) - blockIdx.y;   // heavy tiles first
    int q0 = qblk * 128;

    const size_t tokst = QKV_N;
    const __nv_bfloat16* qh_g = qkv_hi + (size_t)(b * SSZ) * tokst + h * DSZ;
    const __nv_bfloat16* ql_g = qkv_lo + (size_t)(b * SSZ) * tokst + h * DSZ;

    // --- load Q tile (group 0): 2 tiles (hi,lo) x 128 rows x 8 chunks
    #pragma unroll
    for (int t = 0; t < 2; t++) {
        const __nv_bfloat16* src = (t ? ql_g : qh_g);
        uint32_t dst = smb + (t ? AQ_L : AQ_H);
        #pragma unroll
        for (int p = 0; p < 4; p++) {
            int id = p * 256 + tid;             // 1024 per tile
            int r = id >> 3, c = id & 7;
            cp_async16(dst + r * SROWB + c * 16,
                       src + (size_t)(q0 + r) * tokst + c * 8);
        }
    }
    CP_COMMIT();

    auto load_kv = [&](int t, int s) {
        int ks = t * 64;
        uint32_t stg = smb + ASTG0 + s * ASTG_SZ;
        const __nv_bfloat16* bases[4] = {
            qh_g + ESZ, ql_g + ESZ, qh_g + 2 * ESZ, ql_g + 2 * ESZ };
        const int offs[4] = {AKH, AKL, AVH, AVL};
        #pragma unroll
        for (int tile = 0; tile < 4; tile++) {
            #pragma unroll
            for (int p = 0; p < 2; p++) {
                int id = p * 256 + tid;         // 512 per tile
                int r = id >> 3, c = id & 7;
                cp_async16(stg + offs[tile] + r * SROWB + c * 16,
                           bases[tile] + (size_t)(ks + r) * tokst + c * 8);
            }
        }
        CP_COMMIT();
    };

    int ntiles = 2 * qblk + 2;
    load_kv(0, 0);

    float o[8][4];
    #pragma unroll
    for (int nt = 0; nt < 8; nt++)
        #pragma unroll
        for (int c = 0; c < 4; c++) o[nt][c] = 0.f;
    float m1 = -1e30f, m2 = -1e30f, l1 = 0.f, l2 = 0.f;
    uint32_t qfh[4][4], qfl[4][4];

    int lrow = lane & 15, khalf = lane >> 4;
    int qrow0 = wid * 16;

    for (int t = 0; t < ntiles; t++) {
        int s = t & 1;
        if (t + 1 < ntiles) { load_kv(t + 1, s ^ 1); CP_WAIT_1(); }
        else                { CP_WAIT_0(); }
        __syncthreads();
        uint32_t stg = smb + ASTG0 + s * ASTG_SZ;

        if (t == 0) {  // Q fragments (Q smem ready after first wait)
            #pragma unroll
            for (int kd = 0; kd < 4; kd++) {
                uint32_t ro = (qrow0 + lrow) * SROWB + kd * 32 + khalf * 16;
                ldmatrix_x4(qfh[kd], smb + AQ_H + ro);
                ldmatrix_x4(qfl[kd], smb + AQ_L + ro);
            }
        }

        // ---- S = Q K^T (3-pass split) ----
        float sf[8][4];
        #pragma unroll
        for (int nt = 0; nt < 8; nt++)
            #pragma unroll
            for (int c = 0; c < 4; c++) sf[nt][c] = 0.f;

        #pragma unroll
        for (int kd = 0; kd < 4; kd++)
            #pragma unroll
            for (int g = 0; g < 4; g++) {
                uint32_t ro = (g * 16 + lrow) * SROWB + kd * 32 + khalf * 16;
                uint32_t kh4[4], kl4[4];
                ldmatrix_x4(kh4, stg + AKH + ro);
                ldmatrix_x4(kl4, stg + AKL + ro);
                mma_bf16(sf[2 * g],     qfh[kd], kh4[0], kh4[2]);
                mma_bf16(sf[2 * g + 1], qfh[kd], kh4[1], kh4[3]);
                mma_bf16(sf[2 * g],     qfh[kd], kl4[0], kl4[2]);
                mma_bf16(sf[2 * g + 1], qfh[kd], kl4[1], kl4[3]);
                mma_bf16(sf[2 * g],     qfl[kd], kh4[0], kh4[2]);
                mma_bf16(sf[2 * g + 1], qfl[kd], kh4[1], kh4[3]);
            }

        // scale
        #pragma unroll
        for (int nt = 0; nt < 8; nt++)
            #pragma unroll
            for (int c = 0; c < 4; c++) sf[nt][c] *= 0.125f;

        int r1 = q0 + qrow0 + (lane >> 2);   // global q row (and r1+8)

        // causal mask on the two diagonal tiles
        if (t >= 2 * qblk) {
            int ks = t * 64;
            #pragma unroll
            for (int nt = 0; nt < 8; nt++)
                #pragma unroll
                for (int c = 0; c < 4; c++) {
                    int col = ks + nt * 8 + (lane & 3) * 2 + (c & 1);
                    int row = r1 + (c >> 1) * 8;
                    if (col > row) sf[nt][c] = -1e30f;
                }
        }

        // ---- online softmax ----
        float mx1 = -1e30f, mx2 = -1e30f;
        #pragma unroll
        for (int nt = 0; nt < 8; nt++) {
            mx1 = fmaxf(mx1, fmaxf(sf[nt][0], sf[nt][1]));
            mx2 = fmaxf(mx2, fmaxf(sf[nt][2], sf[nt][3]));
        }
        mx1 = fmaxf(mx1, __shfl_xor_sync(0xffffffffu, mx1, 1));
        mx1 = fmaxf(mx1, __shfl_xor_sync(0xffffffffu, mx1, 2));
        mx2 = fmaxf(mx2, __shfl_xor_sync(0xffffffffu, mx2, 1));
        mx2 = fmaxf(mx2, __shfl_xor_sync(0xffffffffu, mx2, 2));
        float mn1 = fmaxf(m1, mx1), mn2 = fmaxf(m2, mx2);
        float a1 = __expf(m1 - mn1), a2 = __expf(m2 - mn2);
        m1 = mn1; m2 = mn2;

        float rs1 = 0.f, rs2 = 0.f;
        #pragma unroll
        for (int nt = 0; nt < 8; nt++) {
            sf[nt][0] = __expf(sf[nt][0] - mn1);
            sf[nt][1] = __expf(sf[nt][1] - mn1);
            sf[nt][2] = __expf(sf[nt][2] - mn2);
            sf[nt][3] = __expf(sf[nt][3] - mn2);
            rs1 += sf[nt][0] + sf[nt][1];
            rs2 += sf[nt][2] + sf[nt][3];
        }
        l1 = l1 * a1 + rs1;      // per-lane partial; reduced at the end
        l2 = l2 * a2 + rs2;
        #pragma unroll
        for (int nt = 0; nt < 8; nt++) {
            o[nt][0] *= a1; o[nt][1] *= a1;
            o[nt][2] *= a2; o[nt][3] *= a2;
        }

        // ---- O += P V (3-pass split; V fragments via ldmatrix.trans) ----
        #pragma unroll
        for (int kp = 0; kp < 4; kp++) {
            uint32_t pah[4], pal[4];
            split2(sf[2 * kp][0],     sf[2 * kp][1],     pah[0], pal[0]);
            split2(sf[2 * kp][2],     sf[2 * kp][3],     pah[1], pal[1]);
            split2(sf[2 * kp + 1][0], sf[2 * kp + 1][1], pah[2], pal[2]);
            split2(sf[2 * kp + 1][2], sf[2 * kp + 1][3], pah[3], pal[3]);
            #pragma unroll
            for (int g = 0; g < 4; g++) {
                uint32_t ro = (kp * 16 + lrow) * SROWB + g * 32 + khalf * 16;
                uint32_t vh4[4], vl4[4];
                ldmatrix_x4_trans(vh4, stg + AVH + ro);
                ldmatrix_x4_trans(vl4, stg + AVL + ro);
                mma_bf16(o[2 * g],     pah, vh4[0], vh4[1]);
                mma_bf16(o[2 * g + 1], pah, vh4[2], vh4[3]);
                mma_bf16(o[2 * g],     pah, vl4[0], vl4[1]);
                mma_bf16(o[2 * g + 1], pah, vl4[2], vl4[3]);
                mma_bf16(o[2 * g],     pal, vh4[0], vh4[1]);
                mma_bf16(o[2 * g + 1], pal, vh4[2], vh4[3]);
            }
        }
        __syncthreads();
    }

    // reduce l across the 4 lanes of each row group
    l1 += __shfl_xor_sync(0xffffffffu, l1, 1);
    l1 += __shfl_xor_sync(0xffffffffu, l1, 2);
    l2 += __shfl_xor_sync(0xffffffffu, l2, 1);
    l2 += __shfl_xor_sync(0xffffffffu, l2, 2);
    float inv1 = 1.0f / l1, inv2 = 1.0f / l2;

    int r1 = b * SSZ + q0 + qrow0 + (lane >> 2);
    size_t base = (size_t)r1 * ESZ + h * DSZ + (lane & 3) * 2;
    #pragma unroll
    for (int nt = 0; nt < 8; nt++) {
        uint32_t h0, l0, h1, l1p;
        split2(o[nt][0] * inv1, o[nt][1] * inv1, h0, l0);
        split2(o[nt][2] * inv2, o[nt][3] * inv2, h1, l1p);
        *(uint32_t*)(ctx_hi + base + nt * 8)            = h0;
        *(uint32_t*)(ctx_lo + base + nt * 8)            = l0;
        *(uint32_t*)(ctx_hi + base + 8 * ESZ + nt * 8)  = h1;
        *(uint32_t*)(ctx_lo + base + 8 * ESZ + nt * 8)  = l1p;
    }
}

// ---------------------------------------------------------------------------
extern "C" void kernel_launch(void* const* d_in, const int* in_sizes, int n_in,
                              void* d_out, int out_size)
{
    const float* x      = (const float*)d_in[0];
    const float* W_attn = (const float*)d_in[1];
    const float* b_attn = (const float*)d_in[2];
    const float* W_proj = (const float*)d_in[3];
    const float* b_proj = (const float*)d_in[4];
    float* out = (float*)d_out;

    __nv_bfloat16 *qkv_hi, *qkv_lo, *xa_hi, *xa_lo, *wat_hi, *wat_lo,
                  *wpt_hi, *wpt_lo, *ctx_hi, *ctx_lo;
    cudaGetSymbolAddress((void**)&qkv_hi, g_qkv_hi);
    cudaGetSymbolAddress((void**)&qkv_lo, g_qkv_lo);
    cudaGetSymbolAddress((void**)&xa_hi, g_xa_hi);
    cudaGetSymbolAddress((void**)&xa_lo, g_xa_lo);
    cudaGetSymbolAddress((void**)&wat_hi, g_wat_hi);
    cudaGetSymbolAddress((void**)&wat_lo, g_wat_lo);
    cudaGetSymbolAddress((void**)&wpt_hi, g_wpt_hi);
    cudaGetSymbolAddress((void**)&wpt_lo, g_wpt_lo);
    cudaGetSymbolAddress((void**)&ctx_hi, g_ctx_hi);
    cudaGetSymbolAddress((void**)&ctx_lo, g_ctx_lo);

    cudaFuncSetAttribute(gemm_mma_split,
                         cudaFuncAttributeMaxDynamicSharedMemorySize, GEMM_SMEM);
    cudaFuncSetAttribute(flash_mma_kernel,
                         cudaFuncAttributeMaxDynamicSharedMemorySize, SMEM_FA);

    // 0) fp32 -> bf16 hi/lo splits
    split_f32<<<(TOKS * KDIM) / (256 * 4), 256>>>((const float4*)x, xa_hi, xa_lo);
    split_transpose<<<dim3(QKV_N / 32, KDIM / 32), dim3(32, 8)>>>(W_attn, wat_hi, wat_lo, QKV_N);
    split_transpose<<<dim3(ESZ / 32, KDIM / 32), dim3(32, 8)>>>(W_proj, wpt_hi, wpt_lo, ESZ);

    // 1) QKV projection -> bf16 hi/lo qkv
    gemm_mma_split<<<dim3(QKV_N / 128, TOKS / 128), 256, GEMM_SMEM>>>(
        xa_hi, xa_lo, wat_hi, wat_lo, b_attn, nullptr, qkv_hi, qkv_lo, QKV_N);

    // 2) Tensor-core causal flash attention -> ctx hi/lo
    flash_mma_kernel<<<dim3(BSZ * HSZ, SSZ / 128), 256, SMEM_FA>>>(
        qkv_hi, qkv_lo, ctx_hi, ctx_lo);

    // 3) Output projection -> fp32 out
    gemm_mma_split<<<dim3(ESZ / 128, TOKS / 128), 256, GEMM_SMEM>>>(
        ctx_hi, ctx_lo, wpt_hi, wpt_lo, b_proj, out, nullptr, nullptr, ESZ);
}

// round 15
// speedup vs baseline: 2.4607x; 1.0039x over previous
#include <cuda_runtime.h>
#include <cuda_bf16.h>
#include <cstdint>

// Problem constants
#define BSZ 2
#define SSZ 2048
#define ESZ 1024
#define HSZ 16
#define DSZ 64
#define TOKS (BSZ*SSZ)          // 4096
#define QKV_N (3*ESZ)           // 3072
#define KDIM 1024               // inner dim of both GEMMs

// ---------------------------------------------------------------------------
// Scratch (no cudaMalloc allowed)
// ---------------------------------------------------------------------------
__device__ __nv_bfloat16 g_qkv_hi[(size_t)TOKS * QKV_N];       // 24 MB
__device__ __nv_bfloat16 g_qkv_lo[(size_t)TOKS * QKV_N];       // 24 MB
__device__ __nv_bfloat16 g_xa_hi[(size_t)TOKS * KDIM];
__device__ __nv_bfloat16 g_xa_lo[(size_t)TOKS * KDIM];
__device__ __nv_bfloat16 g_wat_hi[(size_t)QKV_N * KDIM];       // transposed [N][K]
__device__ __nv_bfloat16 g_wat_lo[(size_t)QKV_N * KDIM];
__device__ __nv_bfloat16 g_wpt_hi[(size_t)ESZ * KDIM];         // transposed [N][K]
__device__ __nv_bfloat16 g_wpt_lo[(size_t)ESZ * KDIM];
__device__ __nv_bfloat16 g_ctx_hi[(size_t)TOKS * ESZ];
__device__ __nv_bfloat16 g_ctx_lo[(size_t)TOKS * ESZ];

// ---------------------------------------------------------------------------
// PTX helpers (all plain-sm_80+ features: valid on compute_103 target)
// ---------------------------------------------------------------------------
__device__ __forceinline__ uint32_t smem_to_u32(const void* p) {
    uint32_t a;
    asm("{ .reg .u64 t; cvta.to.shared.u64 t, %1; cvt.u32.u64 %0, t; }" : "=r"(a) : "l"(p));
    return a;
}
__device__ __forceinline__ void ldmatrix_x4(uint32_t* r, uint32_t addr) {
    asm volatile("ldmatrix.sync.aligned.m8n8.x4.shared.b16 {%0,%1,%2,%3}, [%4];"
        : "=r"(r[0]), "=r"(r[1]), "=r"(r[2]), "=r"(r[3]) : "r"(addr));
}
__device__ __forceinline__ void ldmatrix_x4_trans(uint32_t* r, uint32_t addr) {
    asm volatile("ldmatrix.sync.aligned.m8n8.x4.trans.shared.b16 {%0,%1,%2,%3}, [%4];"
        : "=r"(r[0]), "=r"(r[1]), "=r"(r[2]), "=r"(r[3]) : "r"(addr));
}
__device__ __forceinline__ void mma_bf16(float* d, const uint32_t* a,
                                         uint32_t b0, uint32_t b1) {
    asm volatile("mma.sync.aligned.m16n8k16.row.col.f32.bf16.bf16.f32 "
        "{%0,%1,%2,%3}, {%4,%5,%6,%7}, {%8,%9}, {%0,%1,%2,%3};"
        : "+f"(d[0]), "+f"(d[1]), "+f"(d[2]), "+f"(d[3])
        : "r"(a[0]), "r"(a[1]), "r"(a[2]), "r"(a[3]), "r"(b0), "r"(b1));
}
__device__ __forceinline__ void cp_async16(uint32_t dst, const void* src) {
    asm volatile("cp.async.cg.shared.global [%0], [%1], 16;" :: "r"(dst), "l"(src));
}
#define CP_COMMIT()  asm volatile("cp.async.commit_group;" ::: "memory")
#define CP_WAIT_2()  asm volatile("cp.async.wait_group 2;" ::: "memory")
#define CP_WAIT_1()  asm volatile("cp.async.wait_group 1;" ::: "memory")
#define CP_WAIT_0()  asm volatile("cp.async.wait_group 0;" ::: "memory")

// fp32 pair -> packed bf16x2 hi and lo
__device__ __forceinline__ void split2(float a, float b, uint32_t& hi, uint32_t& lo) {
    __nv_bfloat162 h = __floats2bfloat162_rn(a, b);
    __nv_bfloat162 l = __floats2bfloat162_rn(a - __bfloat162float(h.x),
                                             b - __bfloat162float(h.y));
    hi = *(uint32_t*)&h;
    lo = *(uint32_t*)&l;
}

// ---------------------------------------------------------------------------
// fp32 -> (hi, lo) bf16 split, elementwise (for activations)
// ---------------------------------------------------------------------------
__global__ __launch_bounds__(256) void split_f32(
    const float4* __restrict__ in, __nv_bfloat16* __restrict__ hi,
    __nv_bfloat16* __restrict__ lo)
{
    int i = blockIdx.x * 256 + threadIdx.x;
    float4 v = in[i];
    int o = i * 4;
    uint32_t h0, l0, h1, l1;
    split2(v.x, v.y, h0, l0);
    split2(v.z, v.w, h1, l1);
    *(uint32_t*)(hi + o)     = h0;
    *(uint32_t*)(hi + o + 2) = h1;
    *(uint32_t*)(lo + o)     = l0;
    *(uint32_t*)(lo + o + 2) = l1;
}

// ---------------------------------------------------------------------------
// fp32 W[K][N] -> transposed (hi, lo) bf16 [N][K]
// ---------------------------------------------------------------------------
__global__ __launch_bounds__(256) void split_transpose(
    const float* __restrict__ W, __nv_bfloat16* __restrict__ Th,
    __nv_bfloat16* __restrict__ Tl, int Ncols)
{
    __shared__ float t[32][33];
    int n0 = blockIdx.x * 32, k0 = blockIdx.y * 32;
    int tx = threadIdx.x, ty = threadIdx.y;      // 32 x 8
    #pragma unroll
    for (int p = 0; p < 4; p++)
        t[ty + p * 8][tx] = W[(size_t)(k0 + ty + p * 8) * Ncols + n0 + tx];
    __syncthreads();
    #pragma unroll
    for (int p = 0; p < 4; p++) {
        float v = t[tx][ty + p * 8];
        __nv_bfloat16 h = __float2bfloat16(v);
        size_t o = (size_t)(n0 + ty + p * 8) * KDIM + k0 + tx;
        Th[o] = h;
        Tl[o] = __float2bfloat16(v - __bfloat162float(h));
    }
}

// ---------------------------------------------------------------------------
// mma.sync bf16-split GEMM: C = Ah@Bh^T + Ah@Bl^T + Al@Bh^T + bias
// Output: fp32 C (if Chi==nullptr) else bf16 hi/lo split (Chi/Clo).
// CTA 128x128, BK=32, 8 warps (4m x 2n), warp tile 32x64.
// 4-stage cp.async pipeline (~3 chunks of load latency in flight),
// one __syncthreads per chunk.
// ---------------------------------------------------------------------------
#define TILE_B 10240                 // 128 rows * 80 B
#define STAGE_B (4 * TILE_B)         // Ah, Al, Bh, Bl
#define NSTAGE 4
#define GEMM_SMEM (NSTAGE * STAGE_B) // 163840 B

__global__ __launch_bounds__(256, 1) void gemm_mma_split(
    const __nv_bfloat16* __restrict__ Ah, const __nv_bfloat16* __restrict__ Al,
    const __nv_bfloat16* __restrict__ Bh, const __nv_bfloat16* __restrict__ Bl,
    const float* __restrict__ bias, float* __restrict__ C,
    __nv_bfloat16* __restrict__ Chi, __nv_bfloat16* __restrict__ Clo, int N)
{
    extern __shared__ char sm[];
    uint32_t smb = smem_to_u32(sm);
    int tid = threadIdx.x, wid = tid >> 5, lane = tid & 31;
    int wm = wid & 3, wn = wid >> 2;           // warp coords: 4 x 2
    int m0 = blockIdx.y * 128, n0 = blockIdx.x * 128;

    const __nv_bfloat16* gsrc[4] = {
        Ah + (size_t)m0 * KDIM, Al + (size_t)m0 * KDIM,
        Bh + (size_t)n0 * KDIM, Bl + (size_t)n0 * KDIM };

    int lrow = lane & 15, khalf = lane >> 4;

    float acc[2][8][4];
    #pragma unroll
    for (int mt = 0; mt < 2; mt++)
        #pragma unroll
        for (int nt = 0; nt < 8; nt++)
            #pragma unroll
            for (int c = 0; c < 4; c++) acc[mt][nt][c] = 0.f;

    auto load_chunk = [&](int k0c, int s) {
        uint32_t stb = smb + s * STAGE_B;
        #pragma unroll
        for (int tile = 0; tile < 4; tile++) {
            const __nv_bfloat16* gb = gsrc[tile];
            #pragma unroll
            for (int p = 0; p < 2; p++) {
                int op = p * 256 + tid;
                int row = op >> 2, kg = op & 3;
                cp_async16(stb + tile * TILE_B + row * 80 + kg * 16,
                           gb + (size_t)row * KDIM + k0c + kg * 8);
            }
        }
        CP_COMMIT();
    };

    const int NCHUNK = KDIM / 32;   // 32
    // Prologue: fill 3 of 4 stages
    load_chunk(0, 0);
    load_chunk(32, 1);
    load_chunk(64, 2);

    for (int ch = 0; ch < NCHUNK; ch++) {
        // wait until chunk ch has landed (exact at the tail)
        if (ch <= NCHUNK - 3)      CP_WAIT_2();
        else if (ch == NCHUNK - 2) CP_WAIT_1();
        else                       CP_WAIT_0();
        __syncthreads();   // all warps done with stage (ch+3)%4's previous contents

        if (ch + 3 < NCHUNK)
            load_chunk((ch + 3) * 32, (ch + 3) & (NSTAGE - 1));

        int s = ch & (NSTAGE - 1);
        uint32_t stb = smb + s * STAGE_B;
        uint32_t sAh = stb;
        uint32_t sAl = stb + TILE_B;
        uint32_t sBh = stb + 2 * TILE_B;
        uint32_t sBl = stb + 3 * TILE_B;

        #pragma unroll
        for (int ks = 0; ks < 2; ks++) {
            int koff = ks * 32 + khalf * 16;

            uint32_t ah[2][4], al[2][4];
            #pragma unroll
            for (int mt = 0; mt < 2; mt++) {
                uint32_t ro = (wm * 32 + mt * 16 + lrow) * 80 + koff;
                ldmatrix_x4(ah[mt], sAh + ro);
                ldmatrix_x4(al[mt], sAl + ro);
            }
            uint32_t bh[4][4], bl[4][4];
            #pragma unroll
            for (int g = 0; g < 4; g++) {
                uint32_t ro = (wn * 64 + g * 16 + lrow) * 80 + koff;
                ldmatrix_x4(bh[g], sBh + ro);
                ldmatrix_x4(bl[g], sBl + ro);
            }

            #pragma unroll
            for (int mt = 0; mt < 2; mt++)
                #pragma unroll
                for (int nt = 0; nt < 8; nt++) {
                    int g = nt >> 1, o = nt & 1;
                    mma_bf16(acc[mt][nt], ah[mt], bh[g][o], bh[g][2 + o]);   // hi*hi
                    mma_bf16(acc[mt][nt], ah[mt], bl[g][o], bl[g][2 + o]);   // hi*lo
                    mma_bf16(acc[mt][nt], al[mt], bh[g][o], bh[g][2 + o]);   // lo*hi
                }
        }
    }

    // Epilogue
    int tq = lane >> 2, tr = lane & 3;
    #pragma unroll
    for (int mt = 0; mt < 2; mt++) {
        int rbase = m0 + wm * 32 + mt * 16 + tq;
        #pragma unroll
        for (int nt = 0; nt < 8; nt++) {
            int col = n0 + wn * 64 + nt * 8 + tr * 2;
            float2 bv = *(const float2*)(bias + col);
            float v0 = acc[mt][nt][0] + bv.x, v1 = acc[mt][nt][1] + bv.y;
            float v2 = acc[mt][nt][2] + bv.x, v3 = acc[mt][nt][3] + bv.y;
            if (Chi) {
                uint32_t h0, l0, h1, l1;
                split2(v0, v1, h0, l0);
                split2(v2, v3, h1, l1);
                size_t o0 = (size_t)rbase * N + col;
                size_t o1 = (size_t)(rbase + 8) * N + col;
                *(uint32_t*)(Chi + o0) = h0;  *(uint32_t*)(Clo + o0) = l0;
                *(uint32_t*)(Chi + o1) = h1;  *(uint32_t*)(Clo + o1) = l1;
            } else {
                *(float2*)(C + (size_t)rbase * N + col)       = make_float2(v0, v1);
                *(float2*)(C + (size_t)(rbase + 8) * N + col) = make_float2(v2, v3);
            }
        }
    }
}

// ---------------------------------------------------------------------------
// Tensor-core flash attention (causal). CTA = 128 q rows x one (b,h).
// 8 warps x 16 rows. Bc=64. All GEMMs via mma.sync with 2-term bf16 split.
// Smem rows stride 144 B (72 bf16) -> conflict-free ldmatrix.
// ---------------------------------------------------------------------------
#define SROWB 144
#define AQ_H 0
#define AQ_L 18432
#define ASTG0 36864                     // 2 stages of 36864 after Q
#define ASTG_SZ 36864
#define AKH 0
#define AKL 9216
#define AVH 18432
#define AVL 27648
#define SMEM_FA (ASTG0 + 2 * ASTG_SZ)   // 110592 B

__global__ __launch_bounds__(256, 1) void flash_mma_kernel(
    const __nv_bfloat16* __restrict__ qkv_hi,
    const __nv_bfloat16* __restrict__ qkv_lo,
    __nv_bfloat16* __restrict__ ctx_hi,
    __nv_bfloat16* __restrict__ ctx_lo)
{
    extern __shared__ char sm[];
    uint32_t smb = smem_to_u32(sm);
    int tid = threadIdx.x, wid = tid >> 5, lane = tid & 31;
    int bh = blockIdx.x;
    int b = bh >> 4, h = bh & 15;
    int qblk = (gridDim.y - 1) - blockIdx.y;   // heavy tiles first
    int q0 = qblk * 128;

    const size_t tokst = QKV_N;
    const __nv_bfloat16* qh_g = qkv_hi + (size_t)(b * SSZ) * tokst + h * DSZ;
    const __nv_bfloat16* ql_g = qkv_lo + (size_t)(b * SSZ) * tokst + h * DSZ;

    // --- load Q tile (group 0): 2 tiles (hi,lo) x 128 rows x 8 chunks
    #pragma unroll
    for (int t = 0; t < 2; t++) {
        const __nv_bfloat16* src = (t ? ql_g : qh_g);
        uint32_t dst = smb + (t ? AQ_L : AQ_H);
        #pragma unroll
        for (int p = 0; p < 4; p++) {
            int id = p * 256 + tid;             // 1024 per tile
            int r = id >> 3, c = id & 7;
            cp_async16(dst + r * SROWB + c * 16,
                       src + (size_t)(q0 + r) * tokst + c * 8);
        }
    }
    CP_COMMIT();

    auto load_kv = [&](int t, int s) {
        int ks = t * 64;
        uint32_t stg = smb + ASTG0 + s * ASTG_SZ;
        const __nv_bfloat16* bases[4] = {
            qh_g + ESZ, ql_g + ESZ, qh_g + 2 * ESZ, ql_g + 2 * ESZ };
        const int offs[4] = {AKH, AKL, AVH, AVL};
        #pragma unroll
        for (int tile = 0; tile < 4; tile++) {
            #pragma unroll
            for (int p = 0; p < 2; p++) {
                int id = p * 256 + tid;         // 512 per tile
                int r = id >> 3, c = id & 7;
                cp_async16(stg + offs[tile] + r * SROWB + c * 16,
                           bases[tile] + (size_t)(ks + r) * tokst + c * 8);
            }
        }
        CP_COMMIT();
    };

    int ntiles = 2 * qblk + 2;
    load_kv(0, 0);

    float o[8][4];
    #pragma unroll
    for (int nt = 0; nt < 8; nt++)
        #pragma unroll
        for (int c = 0; c < 4; c++) o[nt][c] = 0.f;
    float m1 = -1e30f, m2 = -1e30f, l1 = 0.f, l2 = 0.f;
    uint32_t qfh[4][4], qfl[4][4];

    int lrow = lane & 15, khalf = lane >> 4;
    int qrow0 = wid * 16;

    for (int t = 0; t < ntiles; t++) {
        int s = t & 1;
        if (t + 1 < ntiles) { load_kv(t + 1, s ^ 1); CP_WAIT_1(); }
        else                { CP_WAIT_0(); }
        __syncthreads();
        uint32_t stg = smb + ASTG0 + s * ASTG_SZ;

        if (t == 0) {  // Q fragments (Q smem ready after first wait)
            #pragma unroll
            for (int kd = 0; kd < 4; kd++) {
                uint32_t ro = (qrow0 + lrow) * SROWB + kd * 32 + khalf * 16;
                ldmatrix_x4(qfh[kd], smb + AQ_H + ro);
                ldmatrix_x4(qfl[kd], smb + AQ_L + ro);
            }
        }

        // ---- S = Q K^T (3-pass split) ----
        float sf[8][4];
        #pragma unroll
        for (int nt = 0; nt < 8; nt++)
            #pragma unroll
            for (int c = 0; c < 4; c++) sf[nt][c] = 0.f;

        #pragma unroll
        for (int kd = 0; kd < 4; kd++)
            #pragma unroll
            for (int g = 0; g < 4; g++) {
                uint32_t ro = (g * 16 + lrow) * SROWB + kd * 32 + khalf * 16;
                uint32_t kh4[4], kl4[4];
                ldmatrix_x4(kh4, stg + AKH + ro);
                ldmatrix_x4(kl4, stg + AKL + ro);
                mma_bf16(sf[2 * g],     qfh[kd], kh4[0], kh4[2]);
                mma_bf16(sf[2 * g + 1], qfh[kd], kh4[1], kh4[3]);
                mma_bf16(sf[2 * g],     qfh[kd], kl4[0], kl4[2]);
                mma_bf16(sf[2 * g + 1], qfh[kd], kl4[1], kl4[3]);
                mma_bf16(sf[2 * g],     qfl[kd], kh4[0], kh4[2]);
                mma_bf16(sf[2 * g + 1], qfl[kd], kh4[1], kh4[3]);
            }

        // scale
        #pragma unroll
        for (int nt = 0; nt < 8; nt++)
            #pragma unroll
            for (int c = 0; c < 4; c++) sf[nt][c] *= 0.125f;

        int r1 = q0 + qrow0 + (lane >> 2);   // global q row (and r1+8)

        // causal mask on the two diagonal tiles
        if (t >= 2 * qblk) {
            int ks = t * 64;
            #pragma unroll
            for (int nt = 0; nt < 8; nt++)
                #pragma unroll
                for (int c = 0; c < 4; c++) {
                    int col = ks + nt * 8 + (lane & 3) * 2 + (c & 1);
                    int row = r1 + (c >> 1) * 8;
                    if (col > row) sf[nt][c] = -1e30f;
                }
        }

        // ---- online softmax ----
        float mx1 = -1e30f, mx2 = -1e30f;
        #pragma unroll
        for (int nt = 0; nt < 8; nt++) {
            mx1 = fmaxf(mx1, fmaxf(sf[nt][0], sf[nt][1]));
            mx2 = fmaxf(mx2, fmaxf(sf[nt][2], sf[nt][3]));
        }
        mx1 = fmaxf(mx1, __shfl_xor_sync(0xffffffffu, mx1, 1));
        mx1 = fmaxf(mx1, __shfl_xor_sync(0xffffffffu, mx1, 2));
        mx2 = fmaxf(mx2, __shfl_xor_sync(0xffffffffu, mx2, 1));
        mx2 = fmaxf(mx2, __shfl_xor_sync(0xffffffffu, mx2, 2));
        float mn1 = fmaxf(m1, mx1), mn2 = fmaxf(m2, mx2);
        float a1 = __expf(m1 - mn1), a2 = __expf(m2 - mn2);
        m1 = mn1; m2 = mn2;

        float rs1 = 0.f, rs2 = 0.f;
        #pragma unroll
        for (int nt = 0; nt < 8; nt++) {
            sf[nt][0] = __expf(sf[nt][0] - mn1);
            sf[nt][1] = __expf(sf[nt][1] - mn1);
            sf[nt][2] = __expf(sf[nt][2] - mn2);
            sf[nt][3] = __expf(sf[nt][3] - mn2);
            rs1 += sf[nt][0] + sf[nt][1];
            rs2 += sf[nt][2] + sf[nt][3];
        }
        l1 = l1 * a1 + rs1;      // per-lane partial; reduced at the end
        l2 = l2 * a2 + rs2;
        #pragma unroll
        for (int nt = 0; nt < 8; nt++) {
            o[nt][0] *= a1; o[nt][1] *= a1;
            o[nt][2] *= a2; o[nt][3] *= a2;
        }

        // ---- O += P V (3-pass split; V fragments via ldmatrix.trans) ----
        #pragma unroll
        for (int kp = 0; kp < 4; kp++) {
            uint32_t pah[4], pal[4];
            split2(sf[2 * kp][0],     sf[2 * kp][1],     pah[0], pal[0]);
            split2(sf[2 * kp][2],     sf[2 * kp][3],     pah[1], pal[1]);
            split2(sf[2 * kp + 1][0], sf[2 * kp + 1][1], pah[2], pal[2]);
            split2(sf[2 * kp + 1][2], sf[2 * kp + 1][3], pah[3], pal[3]);
            #pragma unroll
            for (int g = 0; g < 4; g++) {
                uint32_t ro = (kp * 16 + lrow) * SROWB + g * 32 + khalf * 16;
                uint32_t vh4[4], vl4[4];
                ldmatrix_x4_trans(vh4, stg + AVH + ro);
                ldmatrix_x4_trans(vl4, stg + AVL + ro);
                mma_bf16(o[2 * g],     pah, vh4[0], vh4[1]);
                mma_bf16(o[2 * g + 1], pah, vh4[2], vh4[3]);
                mma_bf16(o[2 * g],     pah, vl4[0], vl4[1]);
                mma_bf16(o[2 * g + 1], pah, vl4[2], vl4[3]);
                mma_bf16(o[2 * g],     pal, vh4[0], vh4[1]);
                mma_bf16(o[2 * g + 1], pal, vh4[2], vh4[3]);
            }
        }
        __syncthreads();
    }

    // reduce l across the 4 lanes of each row group
    l1 += __shfl_xor_sync(0xffffffffu, l1, 1);
    l1 += __shfl_xor_sync(0xffffffffu, l1, 2);
    l2 += __shfl_xor_sync(0xffffffffu, l2, 1);
    l2 += __shfl_xor_sync(0xffffffffu, l2, 2);
    float inv1 = 1.0f / l1, inv2 = 1.0f / l2;

    int r1 = b * SSZ + q0 + qrow0 + (lane >> 2);
    size_t base = (size_t)r1 * ESZ + h * DSZ + (lane & 3) * 2;
    #pragma unroll
    for (int nt = 0; nt < 8; nt++) {
        uint32_t h0, l0, h1, l1p;
        split2(o[nt][0] * inv1, o[nt][1] * inv1, h0, l0);
        split2(o[nt][2] * inv2, o[nt][3] * inv2, h1, l1p);
        *(uint32_t*)(ctx_hi + base + nt * 8)            = h0;
        *(uint32_t*)(ctx_lo + base + nt * 8)            = l0;
        *(uint32_t*)(ctx_hi + base + 8 * ESZ + nt * 8)  = h1;
        *(uint32_t*)(ctx_lo + base + 8 * ESZ + nt * 8)  = l1p;
    }
}

// ---------------------------------------------------------------------------
extern "C" void kernel_launch(void* const* d_in, const int* in_sizes, int n_in,
                              void* d_out, int out_size)
{
    const float* x      = (const float*)d_in[0];
    const float* W_attn = (const float*)d_in[1];
    const float* b_attn = (const float*)d_in[2];
    const float* W_proj = (const float*)d_in[3];
    const float* b_proj = (const float*)d_in[4];
    float* out = (float*)d_out;

    __nv_bfloat16 *qkv_hi, *qkv_lo, *xa_hi, *xa_lo, *wat_hi, *wat_lo,
                  *wpt_hi, *wpt_lo, *ctx_hi, *ctx_lo;
    cudaGetSymbolAddress((void**)&qkv_hi, g_qkv_hi);
    cudaGetSymbolAddress((void**)&qkv_lo, g_qkv_lo);
    cudaGetSymbolAddress((void**)&xa_hi, g_xa_hi);
    cudaGetSymbolAddress((void**)&xa_lo, g_xa_lo);
    cudaGetSymbolAddress((void**)&wat_hi, g_wat_hi);
    cudaGetSymbolAddress((void**)&wat_lo, g_wat_lo);
    cudaGetSymbolAddress((void**)&wpt_hi, g_wpt_hi);
    cudaGetSymbolAddress((void**)&wpt_lo, g_wpt_lo);
    cudaGetSymbolAddress((void**)&ctx_hi, g_ctx_hi);
    cudaGetSymbolAddress((void**)&ctx_lo, g_ctx_lo);

    cudaFuncSetAttribute(gemm_mma_split,
                         cudaFuncAttributeMaxDynamicSharedMemorySize, GEMM_SMEM);
    cudaFuncSetAttribute(flash_mma_kernel,
                         cudaFuncAttributeMaxDynamicSharedMemorySize, SMEM_FA);

    // 0) fp32 -> bf16 hi/lo splits
    split_f32<<<(TOKS * KDIM) / (256 * 4), 256>>>((const float4*)x, xa_hi, xa_lo);
    split_transpose<<<dim3(QKV_N / 32, KDIM / 32), dim3(32, 8)>>>(W_attn, wat_hi, wat_lo, QKV_N);
    split_transpose<<<dim3(ESZ / 32, KDIM / 32), dim3(32, 8)>>>(W_proj, wpt_hi, wpt_lo, ESZ);

    // 1) QKV projection -> bf16 hi/lo qkv
    gemm_mma_split<<<dim3(QKV_N / 128, TOKS / 128), 256, GEMM_SMEM>>>(
        xa_hi, xa_lo, wat_hi, wat_lo, b_attn, nullptr, qkv_hi, qkv_lo, QKV_N);

    // 2) Tensor-core causal flash attention -> ctx hi/lo
    flash_mma_kernel<<<dim3(BSZ * HSZ, SSZ / 128), 256, SMEM_FA>>>(
        qkv_hi, qkv_lo, ctx_hi, ctx_lo);

    // 3) Output projection -> fp32 out
    gemm_mma_split<<<dim3(ESZ / 128, TOKS / 128), 256, GEMM_SMEM>>>(
        ctx_hi, ctx_lo, wpt_hi, wpt_lo, b_proj, out, nullptr, nullptr, ESZ);
}

// round 16
// speedup vs baseline: 2.6518x; 1.0777x over previous
#include <cuda_runtime.h>
#include <cuda_bf16.h>
#include <cstdint>

// Problem constants
#define BSZ 2
#define SSZ 2048
#define ESZ 1024
#define HSZ 16
#define DSZ 64
#define TOKS (BSZ*SSZ)          // 4096
#define QKV_N (3*ESZ)           // 3072
#define KDIM 1024               // inner dim of both GEMMs

// ---------------------------------------------------------------------------
// Scratch (no cudaMalloc allowed)
// ---------------------------------------------------------------------------
__device__ __nv_bfloat16 g_qkv_hi[(size_t)TOKS * QKV_N];       // 24 MB
__device__ __nv_bfloat16 g_qkv_lo[(size_t)TOKS * QKV_N];       // 24 MB
__device__ __nv_bfloat16 g_xa_hi[(size_t)TOKS * KDIM];
__device__ __nv_bfloat16 g_xa_lo[(size_t)TOKS * KDIM];
__device__ __nv_bfloat16 g_wat_hi[(size_t)QKV_N * KDIM];       // transposed [N][K]
__device__ __nv_bfloat16 g_wat_lo[(size_t)QKV_N * KDIM];
__device__ __nv_bfloat16 g_wpt_hi[(size_t)ESZ * KDIM];         // transposed [N][K]
__device__ __nv_bfloat16 g_wpt_lo[(size_t)ESZ * KDIM];
__device__ __nv_bfloat16 g_ctx_hi[(size_t)TOKS * ESZ];
__device__ __nv_bfloat16 g_ctx_lo[(size_t)TOKS * ESZ];

// ---------------------------------------------------------------------------
// PTX helpers (all plain-sm_80+ features: valid on compute_103 target)
// ---------------------------------------------------------------------------
__device__ __forceinline__ uint32_t smem_to_u32(const void* p) {
    uint32_t a;
    asm("{ .reg .u64 t; cvta.to.shared.u64 t, %1; cvt.u32.u64 %0, t; }" : "=r"(a) : "l"(p));
    return a;
}
__device__ __forceinline__ void ldmatrix_x4(uint32_t* r, uint32_t addr) {
    asm volatile("ldmatrix.sync.aligned.m8n8.x4.shared.b16 {%0,%1,%2,%3}, [%4];"
        : "=r"(r[0]), "=r"(r[1]), "=r"(r[2]), "=r"(r[3]) : "r"(addr));
}
__device__ __forceinline__ void ldmatrix_x4_trans(uint32_t* r, uint32_t addr) {
    asm volatile("ldmatrix.sync.aligned.m8n8.x4.trans.shared.b16 {%0,%1,%2,%3}, [%4];"
        : "=r"(r[0]), "=r"(r[1]), "=r"(r[2]), "=r"(r[3]) : "r"(addr));
}
__device__ __forceinline__ void mma_bf16(float* d, const uint32_t* a,
                                         uint32_t b0, uint32_t b1) {
    asm volatile("mma.sync.aligned.m16n8k16.row.col.f32.bf16.bf16.f32 "
        "{%0,%1,%2,%3}, {%4,%5,%6,%7}, {%8,%9}, {%0,%1,%2,%3};"
        : "+f"(d[0]), "+f"(d[1]), "+f"(d[2]), "+f"(d[3])
        : "r"(a[0]), "r"(a[1]), "r"(a[2]), "r"(a[3]), "r"(b0), "r"(b1));
}
__device__ __forceinline__ void cp_async16(uint32_t dst, const void* src) {
    asm volatile("cp.async.cg.shared.global [%0], [%1], 16;" :: "r"(dst), "l"(src));
}
#define CP_COMMIT()  asm volatile("cp.async.commit_group;" ::: "memory")
#define CP_WAIT_1()  asm volatile("cp.async.wait_group 1;" ::: "memory")
#define CP_WAIT_0()  asm volatile("cp.async.wait_group 0;" ::: "memory")

// fp32 pair -> packed bf16x2 hi and lo
__device__ __forceinline__ void split2(float a, float b, uint32_t& hi, uint32_t& lo) {
    __nv_bfloat162 h = __floats2bfloat162_rn(a, b);
    __nv_bfloat162 l = __floats2bfloat162_rn(a - __bfloat162float(h.x),
                                             b - __bfloat162float(h.y));
    hi = *(uint32_t*)&h;
    lo = *(uint32_t*)&l;
}

// ---------------------------------------------------------------------------
// fp32 -> (hi, lo) bf16 split, elementwise (for activations)
// ---------------------------------------------------------------------------
__global__ __launch_bounds__(256) void split_f32(
    const float4* __restrict__ in, __nv_bfloat16* __restrict__ hi,
    __nv_bfloat16* __restrict__ lo)
{
    int i = blockIdx.x * 256 + threadIdx.x;
    float4 v = in[i];
    int o = i * 4;
    uint32_t h0, l0, h1, l1;
    split2(v.x, v.y, h0, l0);
    split2(v.z, v.w, h1, l1);
    *(uint32_t*)(hi + o)     = h0;
    *(uint32_t*)(hi + o + 2) = h1;
    *(uint32_t*)(lo + o)     = l0;
    *(uint32_t*)(lo + o + 2) = l1;
}

// ---------------------------------------------------------------------------
// fp32 W[K][N] -> transposed (hi, lo) bf16 [N][K]
// ---------------------------------------------------------------------------
__global__ __launch_bounds__(256) void split_transpose(
    const float* __restrict__ W, __nv_bfloat16* __restrict__ Th,
    __nv_bfloat16* __restrict__ Tl, int Ncols)
{
    __shared__ float t[32][33];
    int n0 = blockIdx.x * 32, k0 = blockIdx.y * 32;
    int tx = threadIdx.x, ty = threadIdx.y;      // 32 x 8
    #pragma unroll
    for (int p = 0; p < 4; p++)
        t[ty + p * 8][tx] = W[(size_t)(k0 + ty + p * 8) * Ncols + n0 + tx];
    __syncthreads();
    #pragma unroll
    for (int p = 0; p < 4; p++) {
        float v = t[tx][ty + p * 8];
        __nv_bfloat16 h = __float2bfloat16(v);
        size_t o = (size_t)(n0 + ty + p * 8) * KDIM + k0 + tx;
        Th[o] = h;
        Tl[o] = __float2bfloat16(v - __bfloat162float(h));
    }
}

// ---------------------------------------------------------------------------
// mma.sync bf16-split GEMM: C = Ah@Bh^T + Ah@Bl^T + Al@Bh^T + bias
// Output: fp32 C (if Chi==nullptr) else bf16 hi/lo split (Chi/Clo).
// CTA 128x128, BK=32, 8 warps (4m x 2n), warp tile 32x64.
// 2-stage cp.async pipeline, __launch_bounds__(256,2) -> 2 CTAs/SM
// (4 warps/SMSP) to fill tensor-pipe issue slots.
// ---------------------------------------------------------------------------
#define TILE_B 10240                 // 128 rows * 80 B
#define STAGE_B (4 * TILE_B)         // Ah, Al, Bh, Bl
#define GEMM_SMEM (2 * STAGE_B)      // 81920 B (2 CTAs/SM fits 228KB)

__global__ __launch_bounds__(256, 2) void gemm_mma_split(
    const __nv_bfloat16* __restrict__ Ah, const __nv_bfloat16* __restrict__ Al,
    const __nv_bfloat16* __restrict__ Bh, const __nv_bfloat16* __restrict__ Bl,
    const float* __restrict__ bias, float* __restrict__ C,
    __nv_bfloat16* __restrict__ Chi, __nv_bfloat16* __restrict__ Clo, int N)
{
    extern __shared__ char sm[];
    uint32_t smb = smem_to_u32(sm);
    int tid = threadIdx.x, wid = tid >> 5, lane = tid & 31;
    int wm = wid & 3, wn = wid >> 2;           // warp coords: 4 x 2
    int m0 = blockIdx.y * 128, n0 = blockIdx.x * 128;

    const __nv_bfloat16* gsrc[4] = {
        Ah + (size_t)m0 * KDIM, Al + (size_t)m0 * KDIM,
        Bh + (size_t)n0 * KDIM, Bl + (size_t)n0 * KDIM };

    int lrow = lane & 15, khalf = lane >> 4;

    float acc[2][8][4];
    #pragma unroll
    for (int mt = 0; mt < 2; mt++)
        #pragma unroll
        for (int nt = 0; nt < 8; nt++)
            #pragma unroll
            for (int c = 0; c < 4; c++) acc[mt][nt][c] = 0.f;

    auto load_chunk = [&](int k0c, int s) {
        uint32_t stb = smb + s * STAGE_B;
        #pragma unroll
        for (int tile = 0; tile < 4; tile++) {
            const __nv_bfloat16* gb = gsrc[tile];
            #pragma unroll
            for (int p = 0; p < 2; p++) {
                int op = p * 256 + tid;
                int row = op >> 2, kg = op & 3;
                cp_async16(stb + tile * TILE_B + row * 80 + kg * 16,
                           gb + (size_t)row * KDIM + k0c + kg * 8);
            }
        }
        CP_COMMIT();
    };

    load_chunk(0, 0);

    const int NCHUNK = KDIM / 32;   // 32
    for (int ch = 0; ch < NCHUNK; ch++) {
        int s = ch & 1;
        if (ch + 1 < NCHUNK) {
            load_chunk((ch + 1) * 32, s ^ 1);
            CP_WAIT_1();
        } else {
            CP_WAIT_0();
        }
        __syncthreads();

        uint32_t stb = smb + s * STAGE_B;
        uint32_t sAh = stb;
        uint32_t sAl = stb + TILE_B;
        uint32_t sBh = stb + 2 * TILE_B;
        uint32_t sBl = stb + 3 * TILE_B;

        #pragma unroll
        for (int ks = 0; ks < 2; ks++) {
            int koff = ks * 32 + khalf * 16;

            uint32_t ah[2][4], al[2][4];
            #pragma unroll
            for (int mt = 0; mt < 2; mt++) {
                uint32_t ro = (wm * 32 + mt * 16 + lrow) * 80 + koff;
                ldmatrix_x4(ah[mt], sAh + ro);
                ldmatrix_x4(al[mt], sAl + ro);
            }
            uint32_t bh[4][4], bl[4][4];
            #pragma unroll
            for (int g = 0; g < 4; g++) {
                uint32_t ro = (wn * 64 + g * 16 + lrow) * 80 + koff;
                ldmatrix_x4(bh[g], sBh + ro);
                ldmatrix_x4(bl[g], sBl + ro);
            }

            #pragma unroll
            for (int mt = 0; mt < 2; mt++)
                #pragma unroll
                for (int nt = 0; nt < 8; nt++) {
                    int g = nt >> 1, o = nt & 1;
                    mma_bf16(acc[mt][nt], ah[mt], bh[g][o], bh[g][2 + o]);   // hi*hi
                    mma_bf16(acc[mt][nt], ah[mt], bl[g][o], bl[g][2 + o]);   // hi*lo
                    mma_bf16(acc[mt][nt], al[mt], bh[g][o], bh[g][2 + o]);   // lo*hi
                }
        }
        __syncthreads();
    }

    // Epilogue
    int tq = lane >> 2, tr = lane & 3;
    #pragma unroll
    for (int mt = 0; mt < 2; mt++) {
        int rbase = m0 + wm * 32 + mt * 16 + tq;
        #pragma unroll
        for (int nt = 0; nt < 8; nt++) {
            int col = n0 + wn * 64 + nt * 8 + tr * 2;
            float2 bv = *(const float2*)(bias + col);
            float v0 = acc[mt][nt][0] + bv.x, v1 = acc[mt][nt][1] + bv.y;
            float v2 = acc[mt][nt][2] + bv.x, v3 = acc[mt][nt][3] + bv.y;
            if (Chi) {
                uint32_t h0, l0, h1, l1;
                split2(v0, v1, h0, l0);
                split2(v2, v3, h1, l1);
                size_t o0 = (size_t)rbase * N + col;
                size_t o1 = (size_t)(rbase + 8) * N + col;
                *(uint32_t*)(Chi + o0) = h0;  *(uint32_t*)(Clo + o0) = l0;
                *(uint32_t*)(Chi + o1) = h1;  *(uint32_t*)(Clo + o1) = l1;
            } else {
                *(float2*)(C + (size_t)rbase * N + col)       = make_float2(v0, v1);
                *(float2*)(C + (size_t)(rbase + 8) * N + col) = make_float2(v2, v3);
            }
        }
    }
}

// ---------------------------------------------------------------------------
// Tensor-core flash attention (causal). CTA = 128 q rows x one (b,h).
// 8 warps x 16 rows. Bc=64. All GEMMs via mma.sync with 2-term bf16 split.
// Smem rows stride 144 B (72 bf16) -> conflict-free ldmatrix.
// ---------------------------------------------------------------------------
#define SROWB 144
#define AQ_H 0
#define AQ_L 18432
#define ASTG0 36864                     // 2 stages of 36864 after Q
#define ASTG_SZ 36864
#define AKH 0
#define AKL 9216
#define AVH 18432
#define AVL 27648
#define SMEM_FA (ASTG0 + 2 * ASTG_SZ)   // 110592 B

__global__ __launch_bounds__(256, 1) void flash_mma_kernel(
    const __nv_bfloat16* __restrict__ qkv_hi,
    const __nv_bfloat16* __restrict__ qkv_lo,
    __nv_bfloat16* __restrict__ ctx_hi,
    __nv_bfloat16* __restrict__ ctx_lo)
{
    extern __shared__ char sm[];
    uint32_t smb = smem_to_u32(sm);
    int tid = threadIdx.x, wid = tid >> 5, lane = tid & 31;
    int bh = blockIdx.x;
    int b = bh >> 4, h = bh & 15;
    int qblk = (gridDim.y - 1) - blockIdx.y;   // heavy tiles first
    int q0 = qblk * 128;

    const size_t tokst = QKV_N;
    const __nv_bfloat16* qh_g = qkv_hi + (size_t)(b * SSZ) * tokst + h * DSZ;
    const __nv_bfloat16* ql_g = qkv_lo + (size_t)(b * SSZ) * tokst + h * DSZ;

    // --- load Q tile (group 0): 2 tiles (hi,lo) x 128 rows x 8 chunks
    #pragma unroll
    for (int t = 0; t < 2; t++) {
        const __nv_bfloat16* src = (t ? ql_g : qh_g);
        uint32_t dst = smb + (t ? AQ_L : AQ_H);
        #pragma unroll
        for (int p = 0; p < 4; p++) {
            int id = p * 256 + tid;             // 1024 per tile
            int r = id >> 3, c = id & 7;
            cp_async16(dst + r * SROWB + c * 16,
                       src + (size_t)(q0 + r) * tokst + c * 8);
        }
    }
    CP_COMMIT();

    auto load_kv = [&](int t, int s) {
        int ks = t * 64;
        uint32_t stg = smb + ASTG0 + s * ASTG_SZ;
        const __nv_bfloat16* bases[4] = {
            qh_g + ESZ, ql_g + ESZ, qh_g + 2 * ESZ, ql_g + 2 * ESZ };
        const int offs[4] = {AKH, AKL, AVH, AVL};
        #pragma unroll
        for (int tile = 0; tile < 4; tile++) {
            #pragma unroll
            for (int p = 0; p < 2; p++) {
                int id = p * 256 + tid;         // 512 per tile
                int r = id >> 3, c = id & 7;
                cp_async16(stg + offs[tile] + r * SROWB + c * 16,
                           bases[tile] + (size_t)(ks + r) * tokst + c * 8);
            }
        }
        CP_COMMIT();
    };

    int ntiles = 2 * qblk + 2;
    load_kv(0, 0);

    float o[8][4];
    #pragma unroll
    for (int nt = 0; nt < 8; nt++)
        #pragma unroll
        for (int c = 0; c < 4; c++) o[nt][c] = 0.f;
    float m1 = -1e30f, m2 = -1e30f, l1 = 0.f, l2 = 0.f;
    uint32_t qfh[4][4], qfl[4][4];

    int lrow = lane & 15, khalf = lane >> 4;
    int qrow0 = wid * 16;

    for (int t = 0; t < ntiles; t++) {
        int s = t & 1;
        if (t + 1 < ntiles) { load_kv(t + 1, s ^ 1); CP_WAIT_1(); }
        else                { CP_WAIT_0(); }
        __syncthreads();
        uint32_t stg = smb + ASTG0 + s * ASTG_SZ;

        if (t == 0) {  // Q fragments (Q smem ready after first wait)
            #pragma unroll
            for (int kd = 0; kd < 4; kd++) {
                uint32_t ro = (qrow0 + lrow) * SROWB + kd * 32 + khalf * 16;
                ldmatrix_x4(qfh[kd], smb + AQ_H + ro);
                ldmatrix_x4(qfl[kd], smb + AQ_L + ro);
            }
        }

        // ---- S = Q K^T (3-pass split) ----
        float sf[8][4];
        #pragma unroll
        for (int nt = 0; nt < 8; nt++)
            #pragma unroll
            for (int c = 0; c < 4; c++) sf[nt][c] = 0.f;

        #pragma unroll
        for (int kd = 0; kd < 4; kd++)
            #pragma unroll
            for (int g = 0; g < 4; g++) {
                uint32_t ro = (g * 16 + lrow) * SROWB + kd * 32 + khalf * 16;
                uint32_t kh4[4], kl4[4];
                ldmatrix_x4(kh4, stg + AKH + ro);
                ldmatrix_x4(kl4, stg + AKL + ro);
                mma_bf16(sf[2 * g],     qfh[kd], kh4[0], kh4[2]);
                mma_bf16(sf[2 * g + 1], qfh[kd], kh4[1], kh4[3]);
                mma_bf16(sf[2 * g],     qfh[kd], kl4[0], kl4[2]);
                mma_bf16(sf[2 * g + 1], qfh[kd], kl4[1], kl4[3]);
                mma_bf16(sf[2 * g],     qfl[kd], kh4[0], kh4[2]);
                mma_bf16(sf[2 * g + 1], qfl[kd], kh4[1], kh4[3]);
            }

        // scale
        #pragma unroll
        for (int nt = 0; nt < 8; nt++)
            #pragma unroll
            for (int c = 0; c < 4; c++) sf[nt][c] *= 0.125f;

        int r1 = q0 + qrow0 + (lane >> 2);   // global q row (and r1+8)

        // causal mask on the two diagonal tiles
        if (t >= 2 * qblk) {
            int ks = t * 64;
            #pragma unroll
            for (int nt = 0; nt < 8; nt++)
                #pragma unroll
                for (int c = 0; c < 4; c++) {
                    int col = ks + nt * 8 + (lane & 3) * 2 + (c & 1);
                    int row = r1 + (c >> 1) * 8;
                    if (col > row) sf[nt][c] = -1e30f;
                }
        }

        // ---- online softmax ----
        float mx1 = -1e30f, mx2 = -1e30f;
        #pragma unroll
        for (int nt = 0; nt < 8; nt++) {
            mx1 = fmaxf(mx1, fmaxf(sf[nt][0], sf[nt][1]));
            mx2 = fmaxf(mx2, fmaxf(sf[nt][2], sf[nt][3]));
        }
        mx1 = fmaxf(mx1, __shfl_xor_sync(0xffffffffu, mx1, 1));
        mx1 = fmaxf(mx1, __shfl_xor_sync(0xffffffffu, mx1, 2));
        mx2 = fmaxf(mx2, __shfl_xor_sync(0xffffffffu, mx2, 1));
        mx2 = fmaxf(mx2, __shfl_xor_sync(0xffffffffu, mx2, 2));
        float mn1 = fmaxf(m1, mx1), mn2 = fmaxf(m2, mx2);
        float a1 = __expf(m1 - mn1), a2 = __expf(m2 - mn2);
        m1 = mn1; m2 = mn2;

        float rs1 = 0.f, rs2 = 0.f;
        #pragma unroll
        for (int nt = 0; nt < 8; nt++) {
            sf[nt][0] = __expf(sf[nt][0] - mn1);
            sf[nt][1] = __expf(sf[nt][1] - mn1);
            sf[nt][2] = __expf(sf[nt][2] - mn2);
            sf[nt][3] = __expf(sf[nt][3] - mn2);
            rs1 += sf[nt][0] + sf[nt][1];
            rs2 += sf[nt][2] + sf[nt][3];
        }
        l1 = l1 * a1 + rs1;      // per-lane partial; reduced at the end
        l2 = l2 * a2 + rs2;
        #pragma unroll
        for (int nt = 0; nt < 8; nt++) {
            o[nt][0] *= a1; o[nt][1] *= a1;
            o[nt][2] *= a2; o[nt][3] *= a2;
        }

        // ---- O += P V (3-pass split; V fragments via ldmatrix.trans) ----
        #pragma unroll
        for (int kp = 0; kp < 4; kp++) {
            uint32_t pah[4], pal[4];
            split2(sf[2 * kp][0],     sf[2 * kp][1],     pah[0], pal[0]);
            split2(sf[2 * kp][2],     sf[2 * kp][3],     pah[1], pal[1]);
            split2(sf[2 * kp + 1][0], sf[2 * kp + 1][1], pah[2], pal[2]);
            split2(sf[2 * kp + 1][2], sf[2 * kp + 1][3], pah[3], pal[3]);
            #pragma unroll
            for (int g = 0; g < 4; g++) {
                uint32_t ro = (kp * 16 + lrow) * SROWB + g * 32 + khalf * 16;
                uint32_t vh4[4], vl4[4];
                ldmatrix_x4_trans(vh4, stg + AVH + ro);
                ldmatrix_x4_trans(vl4, stg + AVL + ro);
                mma_bf16(o[2 * g],     pah, vh4[0], vh4[1]);
                mma_bf16(o[2 * g + 1], pah, vh4[2], vh4[3]);
                mma_bf16(o[2 * g],     pah, vl4[0], vl4[1]);
                mma_bf16(o[2 * g + 1], pah, vl4[2], vl4[3]);
                mma_bf16(o[2 * g],     pal, vh4[0], vh4[1]);
                mma_bf16(o[2 * g + 1], pal, vh4[2], vh4[3]);
            }
        }
        __syncthreads();
    }

    // reduce l across the 4 lanes of each row group
    l1 += __shfl_xor_sync(0xffffffffu, l1, 1);
    l1 += __shfl_xor_sync(0xffffffffu, l1, 2);
    l2 += __shfl_xor_sync(0xffffffffu, l2, 1);
    l2 += __shfl_xor_sync(0xffffffffu, l2, 2);
    float inv1 = 1.0f / l1, inv2 = 1.0f / l2;

    int r1 = b * SSZ + q0 + qrow0 + (lane >> 2);
    size_t base = (size_t)r1 * ESZ + h * DSZ + (lane & 3) * 2;
    #pragma unroll
    for (int nt = 0; nt < 8; nt++) {
        uint32_t h0, l0, h1, l1p;
        split2(o[nt][0] * inv1, o[nt][1] * inv1, h0, l0);
        split2(o[nt][2] * inv2, o[nt][3] * inv2, h1, l1p);
        *(uint32_t*)(ctx_hi + base + nt * 8)            = h0;
        *(uint32_t*)(ctx_lo + base + nt * 8)            = l0;
        *(uint32_t*)(ctx_hi + base + 8 * ESZ + nt * 8)  = h1;
        *(uint32_t*)(ctx_lo + base + 8 * ESZ + nt * 8)  = l1p;
    }
}

// ---------------------------------------------------------------------------
extern "C" void kernel_launch(void* const* d_in, const int* in_sizes, int n_in,
                              void* d_out, int out_size)
{
    const float* x      = (const float*)d_in[0];
    const float* W_attn = (const float*)d_in[1];
    const float* b_attn = (const float*)d_in[2];
    const float* W_proj = (const float*)d_in[3];
    const float* b_proj = (const float*)d_in[4];
    float* out = (float*)d_out;

    __nv_bfloat16 *qkv_hi, *qkv_lo, *xa_hi, *xa_lo, *wat_hi, *wat_lo,
                  *wpt_hi, *wpt_lo, *ctx_hi, *ctx_lo;
    cudaGetSymbolAddress((void**)&qkv_hi, g_qkv_hi);
    cudaGetSymbolAddress((void**)&qkv_lo, g_qkv_lo);
    cudaGetSymbolAddress((void**)&xa_hi, g_xa_hi);
    cudaGetSymbolAddress((void**)&xa_lo, g_xa_lo);
    cudaGetSymbolAddress((void**)&wat_hi, g_wat_hi);
    cudaGetSymbolAddress((void**)&wat_lo, g_wat_lo);
    cudaGetSymbolAddress((void**)&wpt_hi, g_wpt_hi);
    cudaGetSymbolAddress((void**)&wpt_lo, g_wpt_lo);
    cudaGetSymbolAddress((void**)&ctx_hi, g_ctx_hi);
    cudaGetSymbolAddress((void**)&ctx_lo, g_ctx_lo);

    cudaFuncSetAttribute(gemm_mma_split,
                         cudaFuncAttributeMaxDynamicSharedMemorySize, GEMM_SMEM);
    cudaFuncSetAttribute(flash_mma_kernel,
                         cudaFuncAttributeMaxDynamicSharedMemorySize, SMEM_FA);

    // 0) fp32 -> bf16 hi/lo splits
    split_f32<<<(TOKS * KDIM) / (256 * 4), 256>>>((const float4*)x, xa_hi, xa_lo);
    split_transpose<<<dim3(QKV_N / 32, KDIM / 32), dim3(32, 8)>>>(W_attn, wat_hi, wat_lo, QKV_N);
    split_transpose<<<dim3(ESZ / 32, KDIM / 32), dim3(32, 8)>>>(W_proj, wpt_hi, wpt_lo, ESZ);

    // 1) QKV projection -> bf16 hi/lo qkv
    gemm_mma_split<<<dim3(QKV_N / 128, TOKS / 128), 256, GEMM_SMEM>>>(
        xa_hi, xa_lo, wat_hi, wat_lo, b_attn, nullptr, qkv_hi, qkv_lo, QKV_N);

    // 2) Tensor-core causal flash attention -> ctx hi/lo
    flash_mma_kernel<<<dim3(BSZ * HSZ, SSZ / 128), 256, SMEM_FA>>>(
        qkv_hi, qkv_lo, ctx_hi, ctx_lo);

    // 3) Output projection -> fp32 out
    gemm_mma_split<<<dim3(ESZ / 128, TOKS / 128), 256, GEMM_SMEM>>>(
        ctx_hi, ctx_lo, wpt_hi, wpt_lo, b_proj, out, nullptr, nullptr, ESZ);
}